// round 1
// baseline (speedup 1.0000x reference)
#include <cuda_runtime.h>
#include <cstdint>
#include <cstddef>

#define NN 50000
#define EE 1250000
#define LF 64
#define HF 128
#define EPSV 1e-6f

// ---------------- static device scratch (no allocs allowed) ----------------
__device__ float g_e[(size_t)EE * LF];   // edge latents, permuted into CSR order
__device__ float g_n[(size_t)NN * LF];   // node latents
__device__ float g_x[(size_t)NN * LF];   // MLP input (n + agg)
__device__ int   g_deg[NN];
__device__ int   g_off[NN + 1];
__device__ int   g_cur[NN];
__device__ int   g_slot[EE];             // edge -> CSR slot
__device__ int   g_sperm[EE];            // senders permuted into CSR order

// ---------------- CSR build ----------------
__global__ void k_hist(const int* __restrict__ recv) {
    int i = blockIdx.x * blockDim.x + threadIdx.x;
    if (i < EE) atomicAdd(&g_deg[recv[i]], 1);
}

__global__ void k_scan() {
    __shared__ int sh[1024];
    __shared__ int carry;
    int t = threadIdx.x;
    if (t == 0) carry = 0;
    __syncthreads();
    for (int base = 0; base < NN; base += 1024) {
        int v = (base + t < NN) ? g_deg[base + t] : 0;
        sh[t] = v;
        __syncthreads();
        for (int d = 1; d < 1024; d <<= 1) {
            int x = (t >= d) ? sh[t - d] : 0;
            __syncthreads();
            sh[t] += x;
            __syncthreads();
        }
        int incl = sh[t];
        int total = sh[1023];
        int excl = incl - v + carry;
        if (base + t < NN) { g_off[base + t] = excl; g_cur[base + t] = excl; }
        __syncthreads();
        if (t == 0) carry += total;
        __syncthreads();
    }
    if (t == 0) g_off[NN] = carry;
}

__global__ void k_scatter(const int* __restrict__ recv, const int* __restrict__ send) {
    int i = blockIdx.x * blockDim.x + threadIdx.x;
    if (i < EE) {
        int p = atomicAdd(&g_cur[recv[i]], 1);
        g_slot[i] = p;
        g_sperm[p] = send[i];
    }
}

// ---------------- softmax aggregation: one warp per node, online softmax ----------------
__global__ void k_agg(const float* __restrict__ n, const float* __restrict__ e,
                      const int* __restrict__ sp, const int* __restrict__ off,
                      float* __restrict__ xo) {
    int w = (blockIdx.x * blockDim.x + threadIdx.x) >> 5;
    int lane = threadIdx.x & 31;
    if (w >= NN) return;
    int p0 = __ldg(&off[w]);
    int p1 = __ldg(&off[w + 1]);

    float mx0 = -3.0e38f, mx1 = -3.0e38f;
    float sa0 = 0.f, sb0 = 0.f, sa1 = 0.f, sb1 = 0.f;

    for (int p = p0; p < p1; p++) {
        int s = __ldg(&sp[p]);
        size_t eb = (size_t)p * LF;
        size_t nb = (size_t)s * LF;
        float m0 = fmaxf(n[nb + lane]        + e[eb + lane],        0.f) + EPSV;
        float m1 = fmaxf(n[nb + lane + 32]   + e[eb + lane + 32],   0.f) + EPSV;

        float nm0 = fmaxf(mx0, m0);
        float c0  = __expf(mx0 - nm0);   // 0 on first iteration (-inf)
        float t0  = __expf(m0 - nm0);
        sa0 = sa0 * c0 + t0;
        sb0 = sb0 * c0 + t0 * m0;
        mx0 = nm0;

        float nm1 = fmaxf(mx1, m1);
        float c1  = __expf(mx1 - nm1);
        float t1  = __expf(m1 - nm1);
        sa1 = sa1 * c1 + t1;
        sb1 = sb1 * c1 + t1 * m1;
        mx1 = nm1;
    }
    float a0 = (sa0 > 0.f) ? sb0 / sa0 : 0.f;
    float a1 = (sa1 > 0.f) ? sb1 / sa1 : 0.f;
    size_t nb = (size_t)w * LF;
    xo[nb + lane]      = n[nb + lane]      + a0;
    xo[nb + lane + 32] = n[nb + lane + 32] + a1;
}

// ---------------- fused 3-layer MLP: 128-row tile, 256 threads, 8x8 reg tiles ----------------
// Activations stored TRANSPOSED in shared ([col][row], pad 132) so A-fragments are float4 loads.
template <int IN_F, int OUT_F, bool SCATTER, bool MASK>
__global__ void __launch_bounds__(256, 1)
k_mlp3(const float* __restrict__ X, int rows,
       const float* __restrict__ W0, const float* __restrict__ B0,
       const float* __restrict__ W1, const float* __restrict__ B1,
       const float* __restrict__ W2, const float* __restrict__ B2,
       float* __restrict__ out,
       const int* __restrict__ slot,
       const float* __restrict__ rawn) {
    constexpr int P = 132;
    extern __shared__ float sm[];
    float* H0 = sm;                 // [128][P] transposed
    float* H1 = sm + 128 * P;       // [128][P] transposed
    float* WX = sm + 2 * 128 * P;   // union: (Xs + W0s) then W1s

    const int tid  = threadIdx.x;
    const int tx   = tid & 15;
    const int ty   = tid >> 4;
    const int row0 = blockIdx.x * 128;
    const int r8   = ty * 8;
    const int c8   = tx * 8;

    // ---- stage X (transposed) and W0 ----
    float* Xs  = WX;                // [IN_F][P]
    float* W0s = WX + IN_F * P;     // [IN_F][128]
    for (int idx = tid; idx < 128 * IN_F; idx += 256) {
        int r = idx / IN_F, c = idx - r * IN_F;
        int gr = row0 + r;
        Xs[c * P + r] = (gr < rows) ? X[(size_t)gr * IN_F + c] : 0.f;
    }
    for (int idx = tid; idx < IN_F * HF; idx += 256) W0s[idx] = W0[idx];
    __syncthreads();

    float acc[8][8];
#pragma unroll
    for (int i = 0; i < 8; i++)
#pragma unroll
        for (int j = 0; j < 8; j++) acc[i][j] = 0.f;

    // ---- layer 0 ----
    for (int k = 0; k < IN_F; k++) {
        float4 av0 = *(const float4*)&Xs[k * P + r8];
        float4 av1 = *(const float4*)&Xs[k * P + r8 + 4];
        float4 bv0 = *(const float4*)&W0s[k * HF + c8];
        float4 bv1 = *(const float4*)&W0s[k * HF + c8 + 4];
        float a[8] = {av0.x, av0.y, av0.z, av0.w, av1.x, av1.y, av1.z, av1.w};
        float b[8] = {bv0.x, bv0.y, bv0.z, bv0.w, bv1.x, bv1.y, bv1.z, bv1.w};
#pragma unroll
        for (int i = 0; i < 8; i++)
#pragma unroll
            for (int j = 0; j < 8; j++) acc[i][j] += a[i] * b[j];
    }
    {
        float bb[8];
#pragma unroll
        for (int j = 0; j < 8; j++) bb[j] = __ldg(&B0[c8 + j]);
#pragma unroll
        for (int i = 0; i < 8; i++)
#pragma unroll
            for (int j = 0; j < 8; j++)
                H0[(c8 + j) * P + (r8 + i)] = fmaxf(acc[i][j] + bb[j], 0.f);
    }
    __syncthreads();

    // ---- stage W1 (overwrites Xs/W0s) ----
    float* W1s = WX;
    for (int idx = tid; idx < HF * HF; idx += 256) W1s[idx] = W1[idx];
    __syncthreads();

#pragma unroll
    for (int i = 0; i < 8; i++)
#pragma unroll
        for (int j = 0; j < 8; j++) acc[i][j] = 0.f;

    // ---- layer 1 ----
#pragma unroll 2
    for (int k = 0; k < HF; k++) {
        float4 av0 = *(const float4*)&H0[k * P + r8];
        float4 av1 = *(const float4*)&H0[k * P + r8 + 4];
        float4 bv0 = *(const float4*)&W1s[k * HF + c8];
        float4 bv1 = *(const float4*)&W1s[k * HF + c8 + 4];
        float a[8] = {av0.x, av0.y, av0.z, av0.w, av1.x, av1.y, av1.z, av1.w};
        float b[8] = {bv0.x, bv0.y, bv0.z, bv0.w, bv1.x, bv1.y, bv1.z, bv1.w};
#pragma unroll
        for (int i = 0; i < 8; i++)
#pragma unroll
            for (int j = 0; j < 8; j++) acc[i][j] += a[i] * b[j];
    }
    {
        float bb[8];
#pragma unroll
        for (int j = 0; j < 8; j++) bb[j] = __ldg(&B1[c8 + j]);
#pragma unroll
        for (int i = 0; i < 8; i++)
#pragma unroll
            for (int j = 0; j < 8; j++)
                H1[(c8 + j) * P + (r8 + i)] = fmaxf(acc[i][j] + bb[j], 0.f);
    }
    __syncthreads();

    // ---- stage W2 into (dead) H0 region ----
    float* W2s = H0;
    for (int idx = tid; idx < HF * OUT_F; idx += 256) W2s[idx] = W2[idx];
    __syncthreads();

    // ---- layer 2 (linear) ----
    constexpr int CT = (OUT_F + 15) / 16;
    float a2[8][CT];
#pragma unroll
    for (int i = 0; i < 8; i++)
#pragma unroll
        for (int j = 0; j < CT; j++) a2[i][j] = 0.f;
    const int cc0 = tx * CT;

#pragma unroll 2
    for (int k = 0; k < HF; k++) {
        float4 av0 = *(const float4*)&H1[k * P + r8];
        float4 av1 = *(const float4*)&H1[k * P + r8 + 4];
        float a[8] = {av0.x, av0.y, av0.z, av0.w, av1.x, av1.y, av1.z, av1.w};
        float b[CT];
#pragma unroll
        for (int j = 0; j < CT; j++) {
            int c = cc0 + j;
            b[j] = (c < OUT_F) ? W2s[k * OUT_F + c] : 0.f;
        }
#pragma unroll
        for (int i = 0; i < 8; i++)
#pragma unroll
            for (int j = 0; j < CT; j++) a2[i][j] += a[i] * b[j];
    }

#pragma unroll
    for (int i = 0; i < 8; i++) {
        int r = row0 + r8 + i;
        if (r >= rows) continue;
        float msk = 1.f;
        if (MASK) {
            msk = ((fabsf(rawn[(size_t)r * 2]) + fabsf(rawn[(size_t)r * 2 + 1])) != 0.f) ? 1.f : 0.f;
        }
        int orow = SCATTER ? __ldg(&slot[r]) : r;
#pragma unroll
        for (int j = 0; j < CT; j++) {
            int c = cc0 + j;
            if (c >= OUT_F) continue;
            float v = a2[i][j] + __ldg(&B2[c]);
            out[(size_t)orow * OUT_F + c] = v * msk;
        }
    }
}

static inline int ceilDiv(int a, int b) { return (a + b - 1) / b; }

extern "C" void kernel_launch(void* const* d_in, const int* in_sizes, int n_in,
                              void* d_out, int out_size) {
    (void)in_sizes; (void)n_in; (void)out_size;
    const float* nodes = (const float*)d_in[0];
    const float* edges = (const float*)d_in[1];
    const int*   send  = (const int*)d_in[2];
    const int*   recv  = (const int*)d_in[3];
    const float* enW0 = (const float*)d_in[4],  *enb0 = (const float*)d_in[5];
    const float* enW1 = (const float*)d_in[6],  *enb1 = (const float*)d_in[7];
    const float* enW2 = (const float*)d_in[8],  *enb2 = (const float*)d_in[9];
    const float* eeW0 = (const float*)d_in[10], *eeb0 = (const float*)d_in[11];
    const float* eeW1 = (const float*)d_in[12], *eeb1 = (const float*)d_in[13];
    const float* eeW2 = (const float*)d_in[14], *eeb2 = (const float*)d_in[15];
    const float* pW0  = (const float*)d_in[16], *pb0  = (const float*)d_in[17];
    const float* pW1  = (const float*)d_in[18], *pb1  = (const float*)d_in[19];
    const float* pW2  = (const float*)d_in[20], *pb2  = (const float*)d_in[21];
    const float* dW0  = (const float*)d_in[22], *db0  = (const float*)d_in[23];
    const float* dW1  = (const float*)d_in[24], *db1  = (const float*)d_in[25];
    const float* dW2  = (const float*)d_in[26], *db2  = (const float*)d_in[27];
    float* out = (float*)d_out;

    void *pe, *pn, *px, *pdeg, *poff, *psp, *pslot;
    cudaGetSymbolAddress(&pe, g_e);
    cudaGetSymbolAddress(&pn, g_n);
    cudaGetSymbolAddress(&px, g_x);
    cudaGetSymbolAddress(&pdeg, g_deg);
    cudaGetSymbolAddress(&poff, g_off);
    cudaGetSymbolAddress(&psp, g_sperm);
    cudaGetSymbolAddress(&pslot, g_slot);

    const size_t smem = (size_t)(2 * 128 * 132 + 16640) * sizeof(float);
    cudaFuncSetAttribute(k_mlp3<2, 64, false, false>, cudaFuncAttributeMaxDynamicSharedMemorySize, (int)smem);
    cudaFuncSetAttribute(k_mlp3<3, 64, true,  false>, cudaFuncAttributeMaxDynamicSharedMemorySize, (int)smem);
    cudaFuncSetAttribute(k_mlp3<64, 64, false, false>, cudaFuncAttributeMaxDynamicSharedMemorySize, (int)smem);
    cudaFuncSetAttribute(k_mlp3<64, 2, false, true>,  cudaFuncAttributeMaxDynamicSharedMemorySize, (int)smem);

    // CSR build (by receiver)
    cudaMemsetAsync(pdeg, 0, NN * sizeof(int));
    k_hist<<<ceilDiv(EE, 256), 256>>>(recv);
    k_scan<<<1, 1024>>>();
    k_scatter<<<ceilDiv(EE, 256), 256>>>(recv, send);

    // encoders
    k_mlp3<2, 64, false, false><<<ceilDiv(NN, 128), 256, smem>>>(
        nodes, NN, enW0, enb0, enW1, enb1, enW2, enb2, (float*)pn, nullptr, nullptr);
    k_mlp3<3, 64, true, false><<<ceilDiv(EE, 128), 256, smem>>>(
        edges, EE, eeW0, eeb0, eeW1, eeb1, eeW2, eeb2, (float*)pe, (const int*)pslot, nullptr);

    // processor steps
    for (int s = 0; s < 5; s++) {
        k_agg<<<ceilDiv(NN * 32, 256), 256>>>(
            (const float*)pn, (const float*)pe, (const int*)psp, (const int*)poff, (float*)px);
        k_mlp3<64, 64, false, false><<<ceilDiv(NN, 128), 256, smem>>>(
            (const float*)px, NN,
            pW0 + (size_t)s * 64 * 128, pb0 + (size_t)s * 128,
            pW1 + (size_t)s * 128 * 128, pb1 + (size_t)s * 128,
            pW2 + (size_t)s * 128 * 64,  pb2 + (size_t)s * 64,
            (float*)pn, nullptr, nullptr);
    }

    // decoder + mask
    k_mlp3<64, 2, false, true><<<ceilDiv(NN, 128), 256, smem>>>(
        (const float*)pn, NN, dW0, db0, dW1, db1, dW2, db2, out, nullptr, nodes);
}

// round 2
// speedup vs baseline: 1.0008x; 1.0008x over previous
#include <cuda_runtime.h>
#include <cstdint>
#include <cstddef>

#define NN 50000
#define EE 1250000
#define LF 64
#define HF 128
#define EPSV 1e-6f

// ---------------- static device scratch (no allocs allowed) ----------------
__device__ float g_e[(size_t)EE * LF];   // edge latents, permuted into CSR order
__device__ float g_n[(size_t)NN * LF];   // node latents
__device__ float g_x[(size_t)NN * LF];   // MLP input (n + agg)
__device__ int   g_deg[NN];
__device__ int   g_off[NN + 1];
__device__ int   g_cur[NN];
__device__ int   g_slot[EE];             // edge -> CSR slot
__device__ int   g_sperm[EE];            // senders permuted into CSR order

// ---------------- CSR build ----------------
__global__ void k_hist(const int* __restrict__ recv) {
    int i = blockIdx.x * blockDim.x + threadIdx.x;
    if (i < EE) atomicAdd(&g_deg[recv[i]], 1);
}

__global__ void k_scan() {
    __shared__ int sh[1024];
    __shared__ int carry;
    int t = threadIdx.x;
    if (t == 0) carry = 0;
    __syncthreads();
    for (int base = 0; base < NN; base += 1024) {
        int v = (base + t < NN) ? g_deg[base + t] : 0;
        sh[t] = v;
        __syncthreads();
        for (int d = 1; d < 1024; d <<= 1) {
            int x = (t >= d) ? sh[t - d] : 0;
            __syncthreads();
            sh[t] += x;
            __syncthreads();
        }
        int incl = sh[t];
        int total = sh[1023];
        int excl = incl - v + carry;
        if (base + t < NN) { g_off[base + t] = excl; g_cur[base + t] = excl; }
        __syncthreads();
        if (t == 0) carry += total;
        __syncthreads();
    }
    if (t == 0) g_off[NN] = carry;
}

__global__ void k_scatter(const int* __restrict__ recv, const int* __restrict__ send) {
    int i = blockIdx.x * blockDim.x + threadIdx.x;
    if (i < EE) {
        int p = atomicAdd(&g_cur[recv[i]], 1);
        g_slot[i] = p;
        g_sperm[p] = send[i];
    }
}

// ---------------- softmax aggregation: one warp per node, online softmax ----------------
__global__ void k_agg(const float* __restrict__ n, const float* __restrict__ e,
                      const int* __restrict__ sp, const int* __restrict__ off,
                      float* __restrict__ xo) {
    int w = (blockIdx.x * blockDim.x + threadIdx.x) >> 5;
    int lane = threadIdx.x & 31;
    if (w >= NN) return;
    int p0 = __ldg(&off[w]);
    int p1 = __ldg(&off[w + 1]);

    float mx0 = -3.0e38f, mx1 = -3.0e38f;
    float sa0 = 0.f, sb0 = 0.f, sa1 = 0.f, sb1 = 0.f;

    for (int p = p0; p < p1; p++) {
        int s = __ldg(&sp[p]);
        size_t eb = (size_t)p * LF;
        size_t nb = (size_t)s * LF;
        float m0 = fmaxf(n[nb + lane]        + e[eb + lane],        0.f) + EPSV;
        float m1 = fmaxf(n[nb + lane + 32]   + e[eb + lane + 32],   0.f) + EPSV;

        float nm0 = fmaxf(mx0, m0);
        float c0  = __expf(mx0 - nm0);   // 0 on first iteration (-inf)
        float t0  = __expf(m0 - nm0);
        sa0 = sa0 * c0 + t0;
        sb0 = sb0 * c0 + t0 * m0;
        mx0 = nm0;

        float nm1 = fmaxf(mx1, m1);
        float c1  = __expf(mx1 - nm1);
        float t1  = __expf(m1 - nm1);
        sa1 = sa1 * c1 + t1;
        sb1 = sb1 * c1 + t1 * m1;
        mx1 = nm1;
    }
    float a0 = (sa0 > 0.f) ? sb0 / sa0 : 0.f;
    float a1 = (sa1 > 0.f) ? sb1 / sa1 : 0.f;
    size_t nb = (size_t)w * LF;
    xo[nb + lane]      = n[nb + lane]      + a0;
    xo[nb + lane + 32] = n[nb + lane + 32] + a1;
}

// ---------------- fused 3-layer MLP: 128-row tile, 256 threads, 8x8 reg tiles ----------------
// Activations stored TRANSPOSED in shared ([col][row], pad 132) so A-fragments are float4 loads.
template <int IN_F, int OUT_F, bool SCATTER, bool MASK>
__global__ void __launch_bounds__(256, 1)
k_mlp3(const float* __restrict__ X, int rows,
       const float* __restrict__ W0, const float* __restrict__ B0,
       const float* __restrict__ W1, const float* __restrict__ B1,
       const float* __restrict__ W2, const float* __restrict__ B2,
       float* __restrict__ out,
       const int* __restrict__ slot,
       const float* __restrict__ rawn) {
    constexpr int P = 132;
    extern __shared__ float sm[];
    float* H0 = sm;                 // [128][P] transposed
    float* H1 = sm + 128 * P;       // [128][P] transposed
    float* WX = sm + 2 * 128 * P;   // union: (Xs + W0s) then W1s

    const int tid  = threadIdx.x;
    const int tx   = tid & 15;
    const int ty   = tid >> 4;
    const int row0 = blockIdx.x * 128;
    const int r8   = ty * 8;
    const int c8   = tx * 8;

    // ---- stage X (transposed) and W0 ----
    float* Xs  = WX;                // [IN_F][P]
    float* W0s = WX + IN_F * P;     // [IN_F][128]
    for (int idx = tid; idx < 128 * IN_F; idx += 256) {
        int r = idx / IN_F, c = idx - r * IN_F;
        int gr = row0 + r;
        Xs[c * P + r] = (gr < rows) ? X[(size_t)gr * IN_F + c] : 0.f;
    }
    for (int idx = tid; idx < IN_F * HF; idx += 256) W0s[idx] = W0[idx];
    __syncthreads();

    float acc[8][8];
#pragma unroll
    for (int i = 0; i < 8; i++)
#pragma unroll
        for (int j = 0; j < 8; j++) acc[i][j] = 0.f;

    // ---- layer 0 ----
    for (int k = 0; k < IN_F; k++) {
        float4 av0 = *(const float4*)&Xs[k * P + r8];
        float4 av1 = *(const float4*)&Xs[k * P + r8 + 4];
        float4 bv0 = *(const float4*)&W0s[k * HF + c8];
        float4 bv1 = *(const float4*)&W0s[k * HF + c8 + 4];
        float a[8] = {av0.x, av0.y, av0.z, av0.w, av1.x, av1.y, av1.z, av1.w};
        float b[8] = {bv0.x, bv0.y, bv0.z, bv0.w, bv1.x, bv1.y, bv1.z, bv1.w};
#pragma unroll
        for (int i = 0; i < 8; i++)
#pragma unroll
            for (int j = 0; j < 8; j++) acc[i][j] += a[i] * b[j];
    }
    {
        float bb[8];
#pragma unroll
        for (int j = 0; j < 8; j++) bb[j] = __ldg(&B0[c8 + j]);
#pragma unroll
        for (int i = 0; i < 8; i++)
#pragma unroll
            for (int j = 0; j < 8; j++)
                H0[(c8 + j) * P + (r8 + i)] = fmaxf(acc[i][j] + bb[j], 0.f);
    }
    __syncthreads();

    // ---- stage W1 (overwrites Xs/W0s) ----
    float* W1s = WX;
    for (int idx = tid; idx < HF * HF; idx += 256) W1s[idx] = W1[idx];
    __syncthreads();

#pragma unroll
    for (int i = 0; i < 8; i++)
#pragma unroll
        for (int j = 0; j < 8; j++) acc[i][j] = 0.f;

    // ---- layer 1 ----
#pragma unroll 2
    for (int k = 0; k < HF; k++) {
        float4 av0 = *(const float4*)&H0[k * P + r8];
        float4 av1 = *(const float4*)&H0[k * P + r8 + 4];
        float4 bv0 = *(const float4*)&W1s[k * HF + c8];
        float4 bv1 = *(const float4*)&W1s[k * HF + c8 + 4];
        float a[8] = {av0.x, av0.y, av0.z, av0.w, av1.x, av1.y, av1.z, av1.w};
        float b[8] = {bv0.x, bv0.y, bv0.z, bv0.w, bv1.x, bv1.y, bv1.z, bv1.w};
#pragma unroll
        for (int i = 0; i < 8; i++)
#pragma unroll
            for (int j = 0; j < 8; j++) acc[i][j] += a[i] * b[j];
    }
    {
        float bb[8];
#pragma unroll
        for (int j = 0; j < 8; j++) bb[j] = __ldg(&B1[c8 + j]);
#pragma unroll
        for (int i = 0; i < 8; i++)
#pragma unroll
            for (int j = 0; j < 8; j++)
                H1[(c8 + j) * P + (r8 + i)] = fmaxf(acc[i][j] + bb[j], 0.f);
    }
    __syncthreads();

    // ---- stage W2 into (dead) H0 region ----
    float* W2s = H0;
    for (int idx = tid; idx < HF * OUT_F; idx += 256) W2s[idx] = W2[idx];
    __syncthreads();

    // ---- layer 2 (linear) ----
    constexpr int CT = (OUT_F + 15) / 16;
    float a2[8][CT];
#pragma unroll
    for (int i = 0; i < 8; i++)
#pragma unroll
        for (int j = 0; j < CT; j++) a2[i][j] = 0.f;
    const int cc0 = tx * CT;

#pragma unroll 2
    for (int k = 0; k < HF; k++) {
        float4 av0 = *(const float4*)&H1[k * P + r8];
        float4 av1 = *(const float4*)&H1[k * P + r8 + 4];
        float a[8] = {av0.x, av0.y, av0.z, av0.w, av1.x, av1.y, av1.z, av1.w};
        float b[CT];
#pragma unroll
        for (int j = 0; j < CT; j++) {
            int c = cc0 + j;
            b[j] = (c < OUT_F) ? W2s[k * OUT_F + c] : 0.f;
        }
#pragma unroll
        for (int i = 0; i < 8; i++)
#pragma unroll
            for (int j = 0; j < CT; j++) a2[i][j] += a[i] * b[j];
    }

#pragma unroll
    for (int i = 0; i < 8; i++) {
        int r = row0 + r8 + i;
        if (r >= rows) continue;
        float msk = 1.f;
        if (MASK) {
            msk = ((fabsf(rawn[(size_t)r * 2]) + fabsf(rawn[(size_t)r * 2 + 1])) != 0.f) ? 1.f : 0.f;
        }
        int orow = SCATTER ? __ldg(&slot[r]) : r;
#pragma unroll
        for (int j = 0; j < CT; j++) {
            int c = cc0 + j;
            if (c >= OUT_F) continue;
            float v = a2[i][j] + __ldg(&B2[c]);
            out[(size_t)orow * OUT_F + c] = v * msk;
        }
    }
}

static inline int ceilDiv(int a, int b) { return (a + b - 1) / b; }

extern "C" void kernel_launch(void* const* d_in, const int* in_sizes, int n_in,
                              void* d_out, int out_size) {
    (void)in_sizes; (void)n_in; (void)out_size;
    const float* nodes = (const float*)d_in[0];
    const float* edges = (const float*)d_in[1];
    const int*   send  = (const int*)d_in[2];
    const int*   recv  = (const int*)d_in[3];
    const float* enW0 = (const float*)d_in[4],  *enb0 = (const float*)d_in[5];
    const float* enW1 = (const float*)d_in[6],  *enb1 = (const float*)d_in[7];
    const float* enW2 = (const float*)d_in[8],  *enb2 = (const float*)d_in[9];
    const float* eeW0 = (const float*)d_in[10], *eeb0 = (const float*)d_in[11];
    const float* eeW1 = (const float*)d_in[12], *eeb1 = (const float*)d_in[13];
    const float* eeW2 = (const float*)d_in[14], *eeb2 = (const float*)d_in[15];
    const float* pW0  = (const float*)d_in[16], *pb0  = (const float*)d_in[17];
    const float* pW1  = (const float*)d_in[18], *pb1  = (const float*)d_in[19];
    const float* pW2  = (const float*)d_in[20], *pb2  = (const float*)d_in[21];
    const float* dW0  = (const float*)d_in[22], *db0  = (const float*)d_in[23];
    const float* dW1  = (const float*)d_in[24], *db1  = (const float*)d_in[25];
    const float* dW2  = (const float*)d_in[26], *db2  = (const float*)d_in[27];
    float* out = (float*)d_out;

    void *pe, *pn, *px, *pdeg, *poff, *psp, *pslot;
    cudaGetSymbolAddress(&pe, g_e);
    cudaGetSymbolAddress(&pn, g_n);
    cudaGetSymbolAddress(&px, g_x);
    cudaGetSymbolAddress(&pdeg, g_deg);
    cudaGetSymbolAddress(&poff, g_off);
    cudaGetSymbolAddress(&psp, g_sperm);
    cudaGetSymbolAddress(&pslot, g_slot);

    const size_t smem = (size_t)(2 * 128 * 132 + 16640) * sizeof(float);
    cudaFuncSetAttribute(k_mlp3<2, 64, false, false>, cudaFuncAttributeMaxDynamicSharedMemorySize, (int)smem);
    cudaFuncSetAttribute(k_mlp3<3, 64, true,  false>, cudaFuncAttributeMaxDynamicSharedMemorySize, (int)smem);
    cudaFuncSetAttribute(k_mlp3<64, 64, false, false>, cudaFuncAttributeMaxDynamicSharedMemorySize, (int)smem);
    cudaFuncSetAttribute(k_mlp3<64, 2, false, true>,  cudaFuncAttributeMaxDynamicSharedMemorySize, (int)smem);

    // CSR build (by receiver)
    cudaMemsetAsync(pdeg, 0, NN * sizeof(int));
    k_hist<<<ceilDiv(EE, 256), 256>>>(recv);
    k_scan<<<1, 1024>>>();
    k_scatter<<<ceilDiv(EE, 256), 256>>>(recv, send);

    // encoders
    k_mlp3<2, 64, false, false><<<ceilDiv(NN, 128), 256, smem>>>(
        nodes, NN, enW0, enb0, enW1, enb1, enW2, enb2, (float*)pn, nullptr, nullptr);
    k_mlp3<3, 64, true, false><<<ceilDiv(EE, 128), 256, smem>>>(
        edges, EE, eeW0, eeb0, eeW1, eeb1, eeW2, eeb2, (float*)pe, (const int*)pslot, nullptr);

    // processor steps
    for (int s = 0; s < 5; s++) {
        k_agg<<<ceilDiv(NN * 32, 256), 256>>>(
            (const float*)pn, (const float*)pe, (const int*)psp, (const int*)poff, (float*)px);
        k_mlp3<64, 64, false, false><<<ceilDiv(NN, 128), 256, smem>>>(
            (const float*)px, NN,
            pW0 + (size_t)s * 64 * 128, pb0 + (size_t)s * 128,
            pW1 + (size_t)s * 128 * 128, pb1 + (size_t)s * 128,
            pW2 + (size_t)s * 128 * 64,  pb2 + (size_t)s * 64,
            (float*)pn, nullptr, nullptr);
    }

    // decoder + mask
    k_mlp3<64, 2, false, true><<<ceilDiv(NN, 128), 256, smem>>>(
        (const float*)pn, NN, dW0, db0, dW1, db1, dW2, db2, out, nullptr, nodes);
}

// round 3
// speedup vs baseline: 1.0294x; 1.0286x over previous
#include <cuda_runtime.h>
#include <cstdint>
#include <cstddef>

#define NN 50000
#define EE 1250000
#define LF 64
#define HF 128
#define EPSV 1e-6f

typedef unsigned long long u64t;

// ---------------- packed f32x2 helpers (sm_103a) ----------------
__device__ __forceinline__ u64t pk2(float lo, float hi) {
    u64t r;
    asm("mov.b64 %0, {%1, %2};" : "=l"(r) : "r"(__float_as_uint(lo)), "r"(__float_as_uint(hi)));
    return r;
}
__device__ __forceinline__ u64t pkdup(float v) { return pk2(v, v); }
__device__ __forceinline__ float2 upk(u64t p) {
    unsigned lo, hi;
    asm("mov.b64 {%0, %1}, %2;" : "=r"(lo), "=r"(hi) : "l"(p));
    return make_float2(__uint_as_float(lo), __uint_as_float(hi));
}
__device__ __forceinline__ u64t ffma2_(u64t a, u64t b, u64t c) {
    u64t d;
    asm("fma.rn.f32x2 %0, %1, %2, %3;" : "=l"(d) : "l"(a), "l"(b), "l"(c));
    return d;
}

// ---------------- static device scratch (no allocs allowed) ----------------
__device__ float g_e[(size_t)EE * LF];   // edge latents, permuted into CSR order
__device__ float g_n[(size_t)NN * LF];   // node latents
__device__ float g_x[(size_t)NN * LF];   // MLP input (n + agg)
__device__ int   g_deg[NN];
__device__ int   g_off[NN + 1];
__device__ int   g_cur[NN];
__device__ int   g_slot[EE];             // edge -> CSR slot
__device__ int   g_sperm[EE];            // senders permuted into CSR order

// ---------------- CSR build ----------------
__global__ void k_hist(const int* __restrict__ recv) {
    int i = blockIdx.x * blockDim.x + threadIdx.x;
    if (i < EE) atomicAdd(&g_deg[recv[i]], 1);
}

__global__ void k_scan() {
    __shared__ int sh[1024];
    __shared__ int carry;
    int t = threadIdx.x;
    if (t == 0) carry = 0;
    __syncthreads();
    for (int base = 0; base < NN; base += 1024) {
        int v = (base + t < NN) ? g_deg[base + t] : 0;
        sh[t] = v;
        __syncthreads();
        for (int d = 1; d < 1024; d <<= 1) {
            int x = (t >= d) ? sh[t - d] : 0;
            __syncthreads();
            sh[t] += x;
            __syncthreads();
        }
        int incl = sh[t];
        int total = sh[1023];
        int excl = incl - v + carry;
        if (base + t < NN) { g_off[base + t] = excl; g_cur[base + t] = excl; }
        __syncthreads();
        if (t == 0) carry += total;
        __syncthreads();
    }
    if (t == 0) g_off[NN] = carry;
}

__global__ void k_scatter(const int* __restrict__ recv, const int* __restrict__ send) {
    int i = blockIdx.x * blockDim.x + threadIdx.x;
    if (i < EE) {
        int p = atomicAdd(&g_cur[recv[i]], 1);
        g_slot[i] = p;
        g_sperm[p] = send[i];
    }
}

// ---------------- softmax aggregation: one warp per node, online softmax ----------------
__global__ void k_agg(const float* __restrict__ n, const float* __restrict__ e,
                      const int* __restrict__ sp, const int* __restrict__ off,
                      float* __restrict__ xo) {
    int w = (blockIdx.x * blockDim.x + threadIdx.x) >> 5;
    int lane = threadIdx.x & 31;
    if (w >= NN) return;
    int p0 = __ldg(&off[w]);
    int p1 = __ldg(&off[w + 1]);

    float mx0 = -3.0e38f, mx1 = -3.0e38f;
    float sa0 = 0.f, sb0 = 0.f, sa1 = 0.f, sb1 = 0.f;

    for (int p = p0; p < p1; p++) {
        int s = __ldg(&sp[p]);
        size_t eb = (size_t)p * LF;
        size_t nb = (size_t)s * LF;
        float m0 = fmaxf(n[nb + lane]        + e[eb + lane],        0.f) + EPSV;
        float m1 = fmaxf(n[nb + lane + 32]   + e[eb + lane + 32],   0.f) + EPSV;

        float nm0 = fmaxf(mx0, m0);
        float c0  = __expf(mx0 - nm0);
        float t0  = __expf(m0 - nm0);
        sa0 = sa0 * c0 + t0;
        sb0 = sb0 * c0 + t0 * m0;
        mx0 = nm0;

        float nm1 = fmaxf(mx1, m1);
        float c1  = __expf(mx1 - nm1);
        float t1  = __expf(m1 - nm1);
        sa1 = sa1 * c1 + t1;
        sb1 = sb1 * c1 + t1 * m1;
        mx1 = nm1;
    }
    float a0 = (sa0 > 0.f) ? sb0 / sa0 : 0.f;
    float a1 = (sa1 > 0.f) ? sb1 / sa1 : 0.f;
    size_t nb = (size_t)w * LF;
    xo[nb + lane]      = n[nb + lane]      + a0;
    xo[nb + lane + 32] = n[nb + lane + 32] + a1;
}

// ---------------- fused 3-layer MLP with packed f32x2 FMAs ----------------
// 128-row tile, 256 threads. Per thread: 8 rows x 8 cols, accumulated as
// 4 row-pairs x 8 cols in packed f32x2 (FFMA2 doubles fp32 pipe throughput).
template <int IN_F, int OUT_F, bool SCATTER, bool MASK>
__global__ void __launch_bounds__(256, 1)
k_mlp3(const float* __restrict__ X, int rows,
       const float* __restrict__ W0, const float* __restrict__ B0,
       const float* __restrict__ W1, const float* __restrict__ B1,
       const float* __restrict__ W2, const float* __restrict__ B2,
       float* __restrict__ out,
       const int* __restrict__ slot,
       const float* __restrict__ rawn) {
    constexpr int P = 132;
    extern __shared__ float sm[];
    float* H0 = sm;                 // [128][P] transposed
    float* H1 = sm + 128 * P;       // [128][P] transposed
    float* WX = sm + 2 * 128 * P;   // union: (Xs + W0s) then W1s

    const int tid  = threadIdx.x;
    const int tx   = tid & 15;
    const int ty   = tid >> 4;
    const int row0 = blockIdx.x * 128;
    const int r8   = ty * 8;
    const int c8   = tx * 8;

    // ---- stage X (transposed) and W0 ----
    float* Xs  = WX;                // [IN_F][P]
    float* W0s = WX + IN_F * P;     // [IN_F][128]
    for (int idx = tid; idx < 128 * IN_F; idx += 256) {
        int r = idx / IN_F, c = idx - r * IN_F;
        int gr = row0 + r;
        Xs[c * P + r] = (gr < rows) ? X[(size_t)gr * IN_F + c] : 0.f;
    }
    for (int idx = tid; idx < IN_F * HF; idx += 256) W0s[idx] = W0[idx];
    __syncthreads();

    u64t acc[4][8];
#pragma unroll
    for (int i = 0; i < 4; i++)
#pragma unroll
        for (int j = 0; j < 8; j++) acc[i][j] = 0ull;

    // ---- layer 0 ----
    for (int k = 0; k < IN_F; k++) {
        ulonglong2 aA = *(const ulonglong2*)&Xs[k * P + r8];
        ulonglong2 aB = *(const ulonglong2*)&Xs[k * P + r8 + 4];
        float4 bv0 = *(const float4*)&W0s[k * HF + c8];
        float4 bv1 = *(const float4*)&W0s[k * HF + c8 + 4];
        u64t a2[4] = {aA.x, aA.y, aB.x, aB.y};
        u64t b2[8] = {pkdup(bv0.x), pkdup(bv0.y), pkdup(bv0.z), pkdup(bv0.w),
                      pkdup(bv1.x), pkdup(bv1.y), pkdup(bv1.z), pkdup(bv1.w)};
#pragma unroll
        for (int i = 0; i < 4; i++)
#pragma unroll
            for (int j = 0; j < 8; j++) acc[i][j] = ffma2_(a2[i], b2[j], acc[i][j]);
    }
    {
        float bb[8];
#pragma unroll
        for (int j = 0; j < 8; j++) bb[j] = __ldg(&B0[c8 + j]);
#pragma unroll
        for (int i = 0; i < 4; i++)
#pragma unroll
            for (int j = 0; j < 8; j++) {
                float2 v = upk(acc[i][j]);
                H0[(c8 + j) * P + (r8 + 2 * i)]     = fmaxf(v.x + bb[j], 0.f);
                H0[(c8 + j) * P + (r8 + 2 * i + 1)] = fmaxf(v.y + bb[j], 0.f);
            }
    }
    __syncthreads();

    // ---- stage W1 (overwrites Xs/W0s) ----
    float* W1s = WX;
    for (int idx = tid; idx < HF * HF; idx += 256) W1s[idx] = W1[idx];
    __syncthreads();

#pragma unroll
    for (int i = 0; i < 4; i++)
#pragma unroll
        for (int j = 0; j < 8; j++) acc[i][j] = 0ull;

    // ---- layer 1 ----
#pragma unroll 2
    for (int k = 0; k < HF; k++) {
        ulonglong2 aA = *(const ulonglong2*)&H0[k * P + r8];
        ulonglong2 aB = *(const ulonglong2*)&H0[k * P + r8 + 4];
        float4 bv0 = *(const float4*)&W1s[k * HF + c8];
        float4 bv1 = *(const float4*)&W1s[k * HF + c8 + 4];
        u64t a2[4] = {aA.x, aA.y, aB.x, aB.y};
        u64t b2[8] = {pkdup(bv0.x), pkdup(bv0.y), pkdup(bv0.z), pkdup(bv0.w),
                      pkdup(bv1.x), pkdup(bv1.y), pkdup(bv1.z), pkdup(bv1.w)};
#pragma unroll
        for (int i = 0; i < 4; i++)
#pragma unroll
            for (int j = 0; j < 8; j++) acc[i][j] = ffma2_(a2[i], b2[j], acc[i][j]);
    }
    {
        float bb[8];
#pragma unroll
        for (int j = 0; j < 8; j++) bb[j] = __ldg(&B1[c8 + j]);
#pragma unroll
        for (int i = 0; i < 4; i++)
#pragma unroll
            for (int j = 0; j < 8; j++) {
                float2 v = upk(acc[i][j]);
                H1[(c8 + j) * P + (r8 + 2 * i)]     = fmaxf(v.x + bb[j], 0.f);
                H1[(c8 + j) * P + (r8 + 2 * i + 1)] = fmaxf(v.y + bb[j], 0.f);
            }
    }
    __syncthreads();

    // ---- stage W2 into (dead) H0 region ----
    float* W2s = H0;
    for (int idx = tid; idx < HF * OUT_F; idx += 256) W2s[idx] = W2[idx];
    __syncthreads();

    // ---- layer 2 (linear) ----
    constexpr int CT = (OUT_F + 15) / 16;
    u64t a2c[4][CT];
#pragma unroll
    for (int i = 0; i < 4; i++)
#pragma unroll
        for (int j = 0; j < CT; j++) a2c[i][j] = 0ull;
    const int cc0 = tx * CT;

#pragma unroll 2
    for (int k = 0; k < HF; k++) {
        ulonglong2 aA = *(const ulonglong2*)&H1[k * P + r8];
        ulonglong2 aB = *(const ulonglong2*)&H1[k * P + r8 + 4];
        u64t a2[4] = {aA.x, aA.y, aB.x, aB.y};
        u64t b2[CT];
#pragma unroll
        for (int j = 0; j < CT; j++) {
            int c = cc0 + j;
            b2[j] = pkdup((c < OUT_F) ? W2s[k * OUT_F + c] : 0.f);
        }
#pragma unroll
        for (int i = 0; i < 4; i++)
#pragma unroll
            for (int j = 0; j < CT; j++) a2c[i][j] = ffma2_(a2[i], b2[j], a2c[i][j]);
    }

#pragma unroll
    for (int i = 0; i < 4; i++) {
#pragma unroll
        for (int half = 0; half < 2; half++) {
            int r = row0 + r8 + 2 * i + half;
            if (r >= rows) continue;
            float msk = 1.f;
            if (MASK) {
                msk = ((fabsf(rawn[(size_t)r * 2]) + fabsf(rawn[(size_t)r * 2 + 1])) != 0.f) ? 1.f : 0.f;
            }
            int orow = SCATTER ? __ldg(&slot[r]) : r;
#pragma unroll
            for (int j = 0; j < CT; j++) {
                int c = cc0 + j;
                if (c >= OUT_F) continue;
                float2 v = upk(a2c[i][j]);
                float vv = (half == 0 ? v.x : v.y) + __ldg(&B2[c]);
                out[(size_t)orow * OUT_F + c] = vv * msk;
            }
        }
    }
}

static inline int ceilDiv(int a, int b) { return (a + b - 1) / b; }

extern "C" void kernel_launch(void* const* d_in, const int* in_sizes, int n_in,
                              void* d_out, int out_size) {
    (void)in_sizes; (void)n_in; (void)out_size;
    const float* nodes = (const float*)d_in[0];
    const float* edges = (const float*)d_in[1];
    const int*   send  = (const int*)d_in[2];
    const int*   recv  = (const int*)d_in[3];
    const float* enW0 = (const float*)d_in[4],  *enb0 = (const float*)d_in[5];
    const float* enW1 = (const float*)d_in[6],  *enb1 = (const float*)d_in[7];
    const float* enW2 = (const float*)d_in[8],  *enb2 = (const float*)d_in[9];
    const float* eeW0 = (const float*)d_in[10], *eeb0 = (const float*)d_in[11];
    const float* eeW1 = (const float*)d_in[12], *eeb1 = (const float*)d_in[13];
    const float* eeW2 = (const float*)d_in[14], *eeb2 = (const float*)d_in[15];
    const float* pW0  = (const float*)d_in[16], *pb0  = (const float*)d_in[17];
    const float* pW1  = (const float*)d_in[18], *pb1  = (const float*)d_in[19];
    const float* pW2  = (const float*)d_in[20], *pb2  = (const float*)d_in[21];
    const float* dW0  = (const float*)d_in[22], *db0  = (const float*)d_in[23];
    const float* dW1  = (const float*)d_in[24], *db1  = (const float*)d_in[25];
    const float* dW2  = (const float*)d_in[26], *db2  = (const float*)d_in[27];
    float* out = (float*)d_out;

    void *pe, *pn, *px, *pdeg, *poff, *psp, *pslot;
    cudaGetSymbolAddress(&pe, g_e);
    cudaGetSymbolAddress(&pn, g_n);
    cudaGetSymbolAddress(&px, g_x);
    cudaGetSymbolAddress(&pdeg, g_deg);
    cudaGetSymbolAddress(&poff, g_off);
    cudaGetSymbolAddress(&psp, g_sperm);
    cudaGetSymbolAddress(&pslot, g_slot);

    const size_t smem = (size_t)(2 * 128 * 132 + 16640) * sizeof(float);
    cudaFuncSetAttribute(k_mlp3<2, 64, false, false>, cudaFuncAttributeMaxDynamicSharedMemorySize, (int)smem);
    cudaFuncSetAttribute(k_mlp3<3, 64, true,  false>, cudaFuncAttributeMaxDynamicSharedMemorySize, (int)smem);
    cudaFuncSetAttribute(k_mlp3<64, 64, false, false>, cudaFuncAttributeMaxDynamicSharedMemorySize, (int)smem);
    cudaFuncSetAttribute(k_mlp3<64, 2, false, true>,  cudaFuncAttributeMaxDynamicSharedMemorySize, (int)smem);

    // CSR build (by receiver)
    cudaMemsetAsync(pdeg, 0, NN * sizeof(int));
    k_hist<<<ceilDiv(EE, 256), 256>>>(recv);
    k_scan<<<1, 1024>>>();
    k_scatter<<<ceilDiv(EE, 256), 256>>>(recv, send);

    // encoders
    k_mlp3<2, 64, false, false><<<ceilDiv(NN, 128), 256, smem>>>(
        nodes, NN, enW0, enb0, enW1, enb1, enW2, enb2, (float*)pn, nullptr, nullptr);
    k_mlp3<3, 64, true, false><<<ceilDiv(EE, 128), 256, smem>>>(
        edges, EE, eeW0, eeb0, eeW1, eeb1, eeW2, eeb2, (float*)pe, (const int*)pslot, nullptr);

    // processor steps
    for (int s = 0; s < 5; s++) {
        k_agg<<<ceilDiv(NN * 32, 256), 256>>>(
            (const float*)pn, (const float*)pe, (const int*)psp, (const int*)poff, (float*)px);
        k_mlp3<64, 64, false, false><<<ceilDiv(NN, 128), 256, smem>>>(
            (const float*)px, NN,
            pW0 + (size_t)s * 64 * 128, pb0 + (size_t)s * 128,
            pW1 + (size_t)s * 128 * 128, pb1 + (size_t)s * 128,
            pW2 + (size_t)s * 128 * 64,  pb2 + (size_t)s * 64,
            (float*)pn, nullptr, nullptr);
    }

    // decoder + mask
    k_mlp3<64, 2, false, true><<<ceilDiv(NN, 128), 256, smem>>>(
        (const float*)pn, NN, dW0, db0, dW1, db1, dW2, db2, out, nullptr, nodes);
}

// round 4
// speedup vs baseline: 1.2338x; 1.1985x over previous
#include <cuda_runtime.h>
#include <cstdint>
#include <cstddef>

#define NN 50000
#define EE 1250000
#define LF 64
#define HF 128
#define EPSV 1e-6f

typedef unsigned long long u64t;

// ---------------- packed f32x2 helpers (sm_103a) ----------------
__device__ __forceinline__ u64t pk2(float lo, float hi) {
    u64t r;
    asm("mov.b64 %0, {%1, %2};" : "=l"(r) : "r"(__float_as_uint(lo)), "r"(__float_as_uint(hi)));
    return r;
}
__device__ __forceinline__ u64t pkdup(float v) { return pk2(v, v); }
__device__ __forceinline__ float2 upk(u64t p) {
    unsigned lo, hi;
    asm("mov.b64 {%0, %1}, %2;" : "=r"(lo), "=r"(hi) : "l"(p));
    return make_float2(__uint_as_float(lo), __uint_as_float(hi));
}
__device__ __forceinline__ u64t ffma2_(u64t a, u64t b, u64t c) {
    u64t d;
    asm("fma.rn.f32x2 %0, %1, %2, %3;" : "=l"(d) : "l"(a), "l"(b), "l"(c));
    return d;
}

// ---------------- static device scratch (no allocs allowed) ----------------
__device__ float g_e[(size_t)EE * LF];   // edge latents, permuted into CSR order
__device__ float g_n[(size_t)NN * LF];   // node latents
__device__ float g_x[(size_t)NN * LF];   // MLP input (n + agg)
__device__ int   g_deg[NN];
__device__ int   g_off[NN + 1];
__device__ int   g_cur[NN];
__device__ int   g_slot[EE];             // edge -> CSR slot
__device__ int   g_sperm[EE];            // senders permuted into CSR order

// ---------------- CSR build ----------------
__global__ void k_hist(const int* __restrict__ recv) {
    int i = blockIdx.x * blockDim.x + threadIdx.x;
    if (i < EE) atomicAdd(&g_deg[recv[i]], 1);
}

__global__ void k_scan() {
    __shared__ int sh[1024];
    __shared__ int carry;
    int t = threadIdx.x;
    if (t == 0) carry = 0;
    __syncthreads();
    for (int base = 0; base < NN; base += 1024) {
        int v = (base + t < NN) ? g_deg[base + t] : 0;
        sh[t] = v;
        __syncthreads();
        for (int d = 1; d < 1024; d <<= 1) {
            int x = (t >= d) ? sh[t - d] : 0;
            __syncthreads();
            sh[t] += x;
            __syncthreads();
        }
        int incl = sh[t];
        int total = sh[1023];
        int excl = incl - v + carry;
        if (base + t < NN) { g_off[base + t] = excl; g_cur[base + t] = excl; }
        __syncthreads();
        if (t == 0) carry += total;
        __syncthreads();
    }
    if (t == 0) g_off[NN] = carry;
}

__global__ void k_scatter(const int* __restrict__ recv, const int* __restrict__ send) {
    int i = blockIdx.x * blockDim.x + threadIdx.x;
    if (i < EE) {
        int p = atomicAdd(&g_cur[recv[i]], 1);
        g_slot[i] = p;
        g_sperm[p] = send[i];
    }
}

// ---------------- softmax aggregation: one warp per node, online softmax ----------------
__global__ void k_agg(const float* __restrict__ n, const float* __restrict__ e,
                      const int* __restrict__ sp, const int* __restrict__ off,
                      float* __restrict__ xo) {
    int w = (blockIdx.x * blockDim.x + threadIdx.x) >> 5;
    int lane = threadIdx.x & 31;
    if (w >= NN) return;
    int p0 = __ldg(&off[w]);
    int p1 = __ldg(&off[w + 1]);

    float mx0 = -3.0e38f, mx1 = -3.0e38f;
    float sa0 = 0.f, sb0 = 0.f, sa1 = 0.f, sb1 = 0.f;

    for (int p = p0; p < p1; p++) {
        int s = __ldg(&sp[p]);
        size_t eb = (size_t)p * LF;
        size_t nb = (size_t)s * LF;
        float m0 = fmaxf(n[nb + lane]        + e[eb + lane],        0.f) + EPSV;
        float m1 = fmaxf(n[nb + lane + 32]   + e[eb + lane + 32],   0.f) + EPSV;

        float nm0 = fmaxf(mx0, m0);
        float c0  = __expf(mx0 - nm0);
        float t0  = __expf(m0 - nm0);
        sa0 = sa0 * c0 + t0;
        sb0 = sb0 * c0 + t0 * m0;
        mx0 = nm0;

        float nm1 = fmaxf(mx1, m1);
        float c1  = __expf(mx1 - nm1);
        float t1  = __expf(m1 - nm1);
        sa1 = sa1 * c1 + t1;
        sb1 = sb1 * c1 + t1 * m1;
        mx1 = nm1;
    }
    float a0 = (sa0 > 0.f) ? sb0 / sa0 : 0.f;
    float a1 = (sa1 > 0.f) ? sb1 / sa1 : 0.f;
    size_t nb = (size_t)w * LF;
    xo[nb + lane]      = n[nb + lane]      + a0;
    xo[nb + lane + 32] = n[nb + lane + 32] + a1;
}

// ---------------- fused 3-layer MLP, 2 CTAs/SM ----------------
// Single ping-pong activation buffer H [128][132] (transposed) + one 32KB
// weight-stage buffer WB. W1 staged in two 64-row K-halves. All layer reads
// complete into register accumulators before in-place overwrite (guarded by
// __syncthreads). smem = (128*132 + 64*128)*4 = 100,352 B -> 2 CTAs/SM.
template <int IN_F, int OUT_F, bool SCATTER, bool MASK>
__global__ void __launch_bounds__(256, 2)
k_mlp3(const float* __restrict__ X, int rows,
       const float* __restrict__ W0, const float* __restrict__ B0,
       const float* __restrict__ W1, const float* __restrict__ B1,
       const float* __restrict__ W2, const float* __restrict__ B2,
       float* __restrict__ out,
       const int* __restrict__ slot,
       const float* __restrict__ rawn) {
    constexpr int P = 132;
    static_assert(IN_F <= 64 && OUT_F <= 64, "tile limits");
    extern __shared__ float sm[];
    float* H  = sm;              // [128][P] activations (transposed), ping-pong
    float* WB = sm + 128 * P;    // [64][128] weight staging

    const int tid  = threadIdx.x;
    const int tx   = tid & 15;
    const int ty   = tid >> 4;
    const int row0 = blockIdx.x * 128;
    const int r8   = ty * 8;
    const int c8   = tx * 8;

    // ---- stage X (transposed) into H's first IN_F rows; W0 into WB ----
    for (int idx = tid; idx < 128 * IN_F; idx += 256) {
        int r = idx / IN_F, c = idx - r * IN_F;
        int gr = row0 + r;
        H[c * P + r] = (gr < rows) ? X[(size_t)gr * IN_F + c] : 0.f;
    }
    for (int idx = tid; idx < IN_F * HF; idx += 256) WB[idx] = W0[idx];
    __syncthreads();

    u64t acc[4][8];
#pragma unroll
    for (int i = 0; i < 4; i++)
#pragma unroll
        for (int j = 0; j < 8; j++) acc[i][j] = 0ull;

    // ---- layer 0 ----
    for (int k = 0; k < IN_F; k++) {
        ulonglong2 aA = *(const ulonglong2*)&H[k * P + r8];
        ulonglong2 aB = *(const ulonglong2*)&H[k * P + r8 + 4];
        float4 bv0 = *(const float4*)&WB[k * HF + c8];
        float4 bv1 = *(const float4*)&WB[k * HF + c8 + 4];
        u64t a2[4] = {aA.x, aA.y, aB.x, aB.y};
        u64t b2[8] = {pkdup(bv0.x), pkdup(bv0.y), pkdup(bv0.z), pkdup(bv0.w),
                      pkdup(bv1.x), pkdup(bv1.y), pkdup(bv1.z), pkdup(bv1.w)};
#pragma unroll
        for (int i = 0; i < 4; i++)
#pragma unroll
            for (int j = 0; j < 8; j++) acc[i][j] = ffma2_(a2[i], b2[j], acc[i][j]);
    }
    __syncthreads();   // all Xs/W0 reads done

    // ---- write H0 in place ----
    {
        float bb[8];
#pragma unroll
        for (int j = 0; j < 8; j++) bb[j] = __ldg(&B0[c8 + j]);
#pragma unroll
        for (int i = 0; i < 4; i++)
#pragma unroll
            for (int j = 0; j < 8; j++) {
                float2 v = upk(acc[i][j]);
                H[(c8 + j) * P + (r8 + 2 * i)]     = fmaxf(v.x + bb[j], 0.f);
                H[(c8 + j) * P + (r8 + 2 * i + 1)] = fmaxf(v.y + bb[j], 0.f);
            }
    }

#pragma unroll
    for (int i = 0; i < 4; i++)
#pragma unroll
        for (int j = 0; j < 8; j++) acc[i][j] = 0ull;

    // ---- layer 1: two K-halves, W1 staged through WB ----
#pragma unroll
    for (int half = 0; half < 2; half++) {
        __syncthreads();   // H0 written (half 0) / previous WB reads done (half 1)
        for (int idx = tid; idx < 64 * HF; idx += 256)
            WB[idx] = W1[(size_t)half * 64 * HF + idx];
        __syncthreads();
#pragma unroll 2
        for (int k = 0; k < 64; k++) {
            int kk = half * 64 + k;
            ulonglong2 aA = *(const ulonglong2*)&H[kk * P + r8];
            ulonglong2 aB = *(const ulonglong2*)&H[kk * P + r8 + 4];
            float4 bv0 = *(const float4*)&WB[k * HF + c8];
            float4 bv1 = *(const float4*)&WB[k * HF + c8 + 4];
            u64t a2[4] = {aA.x, aA.y, aB.x, aB.y};
            u64t b2[8] = {pkdup(bv0.x), pkdup(bv0.y), pkdup(bv0.z), pkdup(bv0.w),
                          pkdup(bv1.x), pkdup(bv1.y), pkdup(bv1.z), pkdup(bv1.w)};
#pragma unroll
            for (int i = 0; i < 4; i++)
#pragma unroll
                for (int j = 0; j < 8; j++) acc[i][j] = ffma2_(a2[i], b2[j], acc[i][j]);
        }
    }
    __syncthreads();   // all H0 / W1 reads done

    // ---- write H1 in place; stage W2 into WB ----
    {
        float bb[8];
#pragma unroll
        for (int j = 0; j < 8; j++) bb[j] = __ldg(&B1[c8 + j]);
#pragma unroll
        for (int i = 0; i < 4; i++)
#pragma unroll
            for (int j = 0; j < 8; j++) {
                float2 v = upk(acc[i][j]);
                H[(c8 + j) * P + (r8 + 2 * i)]     = fmaxf(v.x + bb[j], 0.f);
                H[(c8 + j) * P + (r8 + 2 * i + 1)] = fmaxf(v.y + bb[j], 0.f);
            }
    }
    for (int idx = tid; idx < HF * OUT_F; idx += 256) WB[idx] = W2[idx];
    __syncthreads();

    // ---- layer 2 (linear) ----
    constexpr int CT = (OUT_F + 15) / 16;
    u64t a2c[4][CT];
#pragma unroll
    for (int i = 0; i < 4; i++)
#pragma unroll
        for (int j = 0; j < CT; j++) a2c[i][j] = 0ull;
    const int cc0 = tx * CT;

#pragma unroll 2
    for (int k = 0; k < HF; k++) {
        ulonglong2 aA = *(const ulonglong2*)&H[k * P + r8];
        ulonglong2 aB = *(const ulonglong2*)&H[k * P + r8 + 4];
        u64t a2[4] = {aA.x, aA.y, aB.x, aB.y};
        u64t b2[CT];
#pragma unroll
        for (int j = 0; j < CT; j++) {
            int c = cc0 + j;
            b2[j] = pkdup((c < OUT_F) ? WB[k * OUT_F + c] : 0.f);
        }
#pragma unroll
        for (int i = 0; i < 4; i++)
#pragma unroll
            for (int j = 0; j < CT; j++) a2c[i][j] = ffma2_(a2[i], b2[j], a2c[i][j]);
    }

#pragma unroll
    for (int i = 0; i < 4; i++) {
#pragma unroll
        for (int half = 0; half < 2; half++) {
            int r = row0 + r8 + 2 * i + half;
            if (r >= rows) continue;
            float msk = 1.f;
            if (MASK) {
                msk = ((fabsf(rawn[(size_t)r * 2]) + fabsf(rawn[(size_t)r * 2 + 1])) != 0.f) ? 1.f : 0.f;
            }
            int orow = SCATTER ? __ldg(&slot[r]) : r;
#pragma unroll
            for (int j = 0; j < CT; j++) {
                int c = cc0 + j;
                if (c >= OUT_F) continue;
                float2 v = upk(a2c[i][j]);
                float vv = (half == 0 ? v.x : v.y) + __ldg(&B2[c]);
                out[(size_t)orow * OUT_F + c] = vv * msk;
            }
        }
    }
}

static inline int ceilDiv(int a, int b) { return (a + b - 1) / b; }

extern "C" void kernel_launch(void* const* d_in, const int* in_sizes, int n_in,
                              void* d_out, int out_size) {
    (void)in_sizes; (void)n_in; (void)out_size;
    const float* nodes = (const float*)d_in[0];
    const float* edges = (const float*)d_in[1];
    const int*   send  = (const int*)d_in[2];
    const int*   recv  = (const int*)d_in[3];
    const float* enW0 = (const float*)d_in[4],  *enb0 = (const float*)d_in[5];
    const float* enW1 = (const float*)d_in[6],  *enb1 = (const float*)d_in[7];
    const float* enW2 = (const float*)d_in[8],  *enb2 = (const float*)d_in[9];
    const float* eeW0 = (const float*)d_in[10], *eeb0 = (const float*)d_in[11];
    const float* eeW1 = (const float*)d_in[12], *eeb1 = (const float*)d_in[13];
    const float* eeW2 = (const float*)d_in[14], *eeb2 = (const float*)d_in[15];
    const float* pW0  = (const float*)d_in[16], *pb0  = (const float*)d_in[17];
    const float* pW1  = (const float*)d_in[18], *pb1  = (const float*)d_in[19];
    const float* pW2  = (const float*)d_in[20], *pb2  = (const float*)d_in[21];
    const float* dW0  = (const float*)d_in[22], *db0  = (const float*)d_in[23];
    const float* dW1  = (const float*)d_in[24], *db1  = (const float*)d_in[25];
    const float* dW2  = (const float*)d_in[26], *db2  = (const float*)d_in[27];
    float* out = (float*)d_out;

    void *pe, *pn, *px, *pdeg, *poff, *psp, *pslot;
    cudaGetSymbolAddress(&pe, g_e);
    cudaGetSymbolAddress(&pn, g_n);
    cudaGetSymbolAddress(&px, g_x);
    cudaGetSymbolAddress(&pdeg, g_deg);
    cudaGetSymbolAddress(&poff, g_off);
    cudaGetSymbolAddress(&psp, g_sperm);
    cudaGetSymbolAddress(&pslot, g_slot);

    const size_t smem = (size_t)(128 * 132 + 64 * 128) * sizeof(float);  // 100,352 B
    cudaFuncSetAttribute(k_mlp3<2, 64, false, false>, cudaFuncAttributeMaxDynamicSharedMemorySize, (int)smem);
    cudaFuncSetAttribute(k_mlp3<3, 64, true,  false>, cudaFuncAttributeMaxDynamicSharedMemorySize, (int)smem);
    cudaFuncSetAttribute(k_mlp3<64, 64, false, false>, cudaFuncAttributeMaxDynamicSharedMemorySize, (int)smem);
    cudaFuncSetAttribute(k_mlp3<64, 2, false, true>,  cudaFuncAttributeMaxDynamicSharedMemorySize, (int)smem);

    // CSR build (by receiver)
    cudaMemsetAsync(pdeg, 0, NN * sizeof(int));
    k_hist<<<ceilDiv(EE, 256), 256>>>(recv);
    k_scan<<<1, 1024>>>();
    k_scatter<<<ceilDiv(EE, 256), 256>>>(recv, send);

    // encoders
    k_mlp3<2, 64, false, false><<<ceilDiv(NN, 128), 256, smem>>>(
        nodes, NN, enW0, enb0, enW1, enb1, enW2, enb2, (float*)pn, nullptr, nullptr);
    k_mlp3<3, 64, true, false><<<ceilDiv(EE, 128), 256, smem>>>(
        edges, EE, eeW0, eeb0, eeW1, eeb1, eeW2, eeb2, (float*)pe, (const int*)pslot, nullptr);

    // processor steps
    for (int s = 0; s < 5; s++) {
        k_agg<<<ceilDiv(NN * 32, 256), 256>>>(
            (const float*)pn, (const float*)pe, (const int*)psp, (const int*)poff, (float*)px);
        k_mlp3<64, 64, false, false><<<ceilDiv(NN, 128), 256, smem>>>(
            (const float*)px, NN,
            pW0 + (size_t)s * 64 * 128, pb0 + (size_t)s * 128,
            pW1 + (size_t)s * 128 * 128, pb1 + (size_t)s * 128,
            pW2 + (size_t)s * 128 * 64,  pb2 + (size_t)s * 64,
            (float*)pn, nullptr, nullptr);
    }

    // decoder + mask
    k_mlp3<64, 2, false, true><<<ceilDiv(NN, 128), 256, smem>>>(
        (const float*)pn, NN, dW0, db0, dW1, db1, dW2, db2, out, nullptr, nodes);
}

// round 6
// speedup vs baseline: 1.4854x; 1.2040x over previous
#include <cuda_runtime.h>
#include <cuda_bf16.h>
#include <cstdint>
#include <cstddef>

#define NN 50000
#define EE 1250000
#define LF 64
#define HF 128
#define EPSV 1e-6f

// ---------------- static device scratch (no allocs allowed) ----------------
__device__ float g_e[(size_t)EE * LF];                 // edge latents (CSR order)
__device__ float g_n[(size_t)(NN + 128) * LF];         // node latents (padded)
__device__ __nv_bfloat16 g_xh[(size_t)(NN + 128) * LF];// processor input hi (padded)
__device__ __nv_bfloat16 g_xl[(size_t)(NN + 128) * LF];// processor input lo (padded)
__device__ __nv_bfloat16 g_wt[22 * 32768];             // weights: [N][K] bf16, hi then lo(+16384)
__device__ int g_deg[NN];
__device__ int g_off[NN + 1];
__device__ int g_cur[NN];
__device__ int g_slot[EE];
__device__ int g_sperm[EE];

// ---------------- CSR build ----------------
__global__ void k_hist(const int* __restrict__ recv) {
    int i = blockIdx.x * blockDim.x + threadIdx.x;
    if (i < EE) atomicAdd(&g_deg[recv[i]], 1);
}

__global__ void k_scan() {
    __shared__ int sh[1024];
    __shared__ int carry;
    int t = threadIdx.x;
    if (t == 0) carry = 0;
    __syncthreads();
    for (int base = 0; base < NN; base += 1024) {
        int v = (base + t < NN) ? g_deg[base + t] : 0;
        sh[t] = v;
        __syncthreads();
        for (int d = 1; d < 1024; d <<= 1) {
            int x = (t >= d) ? sh[t - d] : 0;
            __syncthreads();
            sh[t] += x;
            __syncthreads();
        }
        int incl = sh[t];
        int total = sh[1023];
        int excl = incl - v + carry;
        if (base + t < NN) { g_off[base + t] = excl; g_cur[base + t] = excl; }
        __syncthreads();
        if (t == 0) carry += total;
        __syncthreads();
    }
    if (t == 0) g_off[NN] = carry;
}

__global__ void k_scatter(const int* __restrict__ recv, const int* __restrict__ send) {
    int i = blockIdx.x * blockDim.x + threadIdx.x;
    if (i < EE) {
        int p = atomicAdd(&g_cur[recv[i]], 1);
        g_slot[i] = p;
        g_sperm[p] = send[i];
    }
}

// ---------------- weight prep: fp32 [K][N] -> bf16 hi/lo [N][K] ----------------
struct WSlot { const float* src; int N; int K; };
struct WTable { WSlot s[22]; };

__global__ void k_prep(WTable tab) {
    int m = blockIdx.y;
    WSlot sl = tab.s[m];
    int total = sl.N * sl.K;
    int e = blockIdx.x * 256 + threadIdx.x;
    if (e >= total) return;
    int k = e / sl.N;
    int n = e - k * sl.N;
    float v = __ldg(&sl.src[e]);
    __nv_bfloat16 h = __float2bfloat16(v);
    __nv_bfloat16 l = __float2bfloat16(v - __bfloat162float(h));
    size_t off = (size_t)m * 32768 + (size_t)n * sl.K + k;
    g_wt[off] = h;
    g_wt[off + 16384] = l;
}

// ---------------- softmax aggregation (emits pre-split bf16 x) ----------------
__global__ void k_agg(const float* __restrict__ n, const float* __restrict__ e,
                      const int* __restrict__ sp, const int* __restrict__ off,
                      __nv_bfloat16* __restrict__ xh, __nv_bfloat16* __restrict__ xl) {
    int w = (blockIdx.x * blockDim.x + threadIdx.x) >> 5;
    int lane = threadIdx.x & 31;
    if (w >= NN) return;
    int p0 = __ldg(&off[w]);
    int p1 = __ldg(&off[w + 1]);

    float mx0 = -3.0e38f, mx1 = -3.0e38f;
    float sa0 = 0.f, sb0 = 0.f, sa1 = 0.f, sb1 = 0.f;

    for (int p = p0; p < p1; p++) {
        int s = __ldg(&sp[p]);
        size_t eb = (size_t)p * LF;
        size_t nb = (size_t)s * LF;
        float m0 = fmaxf(n[nb + lane]      + e[eb + lane],      0.f) + EPSV;
        float m1 = fmaxf(n[nb + lane + 32] + e[eb + lane + 32], 0.f) + EPSV;

        float nm0 = fmaxf(mx0, m0);
        float c0  = __expf(mx0 - nm0);
        float t0  = __expf(m0 - nm0);
        sa0 = sa0 * c0 + t0;
        sb0 = sb0 * c0 + t0 * m0;
        mx0 = nm0;

        float nm1 = fmaxf(mx1, m1);
        float c1  = __expf(mx1 - nm1);
        float t1  = __expf(m1 - nm1);
        sa1 = sa1 * c1 + t1;
        sb1 = sb1 * c1 + t1 * m1;
        mx1 = nm1;
    }
    float a0 = (sa0 > 0.f) ? sb0 / sa0 : 0.f;
    float a1 = (sa1 > 0.f) ? sb1 / sa1 : 0.f;
    size_t nb = (size_t)w * LF;
    float x0 = n[nb + lane]      + a0;
    float x1 = n[nb + lane + 32] + a1;
    __nv_bfloat16 h0 = __float2bfloat16(x0);
    __nv_bfloat16 h1 = __float2bfloat16(x1);
    xh[nb + lane]      = h0;
    xl[nb + lane]      = __float2bfloat16(x0 - __bfloat162float(h0));
    xh[nb + lane + 32] = h1;
    xl[nb + lane + 32] = __float2bfloat16(x1 - __bfloat162float(h1));
}

// ---------------- mma.sync helpers ----------------
__device__ __forceinline__ void mma_bf16(float* c, uint32_t a0, uint32_t a1, uint32_t a2, uint32_t a3,
                                         uint32_t b0, uint32_t b1) {
    asm volatile("mma.sync.aligned.m16n8k16.row.col.f32.bf16.bf16.f32 "
                 "{%0,%1,%2,%3}, {%4,%5,%6,%7}, {%8,%9}, {%0,%1,%2,%3};"
                 : "+f"(c[0]), "+f"(c[1]), "+f"(c[2]), "+f"(c[3])
                 : "r"(a0), "r"(a1), "r"(a2), "r"(a3), "r"(b0), "r"(b1));
}

__device__ __forceinline__ void split_pack(float a, float b, uint32_t& hi, uint32_t& lo) {
    __nv_bfloat16 ha = __float2bfloat16(a), hb = __float2bfloat16(b);
    float ra = a - __bfloat162float(ha), rb = b - __bfloat162float(hb);
    hi = (uint32_t)__bfloat16_as_ushort(ha) | ((uint32_t)__bfloat16_as_ushort(hb) << 16);
    lo = (uint32_t)__bfloat16_as_ushort(__float2bfloat16(ra)) |
         ((uint32_t)__bfloat16_as_ushort(__float2bfloat16(rb)) << 16);
}

#define SP 136  // smem row stride (bf16 units): conflict-free fragment loads

// 3-pass (hh + hl + lh) bf16 GEMM on a 128-row tile; warp owns rows [mb, mb+16)
template <int NT, int KST>
__device__ __forceinline__ void gemm_sm(const __nv_bfloat16* Ah, const __nv_bfloat16* Al,
                                        const __nv_bfloat16* Bh, const __nv_bfloat16* Bl,
                                        int mb, int g, int tg, float acc[][4]) {
#pragma unroll
    for (int k = 0; k < KST; k++) {
        int k0 = k * 16 + tg * 2;
        uint32_t ah0 = *(const uint32_t*)(Ah + (mb + g) * SP + k0);
        uint32_t ah1 = *(const uint32_t*)(Ah + (mb + g + 8) * SP + k0);
        uint32_t ah2 = *(const uint32_t*)(Ah + (mb + g) * SP + k0 + 8);
        uint32_t ah3 = *(const uint32_t*)(Ah + (mb + g + 8) * SP + k0 + 8);
        uint32_t al0 = *(const uint32_t*)(Al + (mb + g) * SP + k0);
        uint32_t al1 = *(const uint32_t*)(Al + (mb + g + 8) * SP + k0);
        uint32_t al2 = *(const uint32_t*)(Al + (mb + g) * SP + k0 + 8);
        uint32_t al3 = *(const uint32_t*)(Al + (mb + g + 8) * SP + k0 + 8);
#pragma unroll
        for (int t = 0; t < NT; t++) {
            int nb = t * 8 + g;
            uint32_t bh0 = *(const uint32_t*)(Bh + nb * SP + k0);
            uint32_t bh1 = *(const uint32_t*)(Bh + nb * SP + k0 + 8);
            uint32_t bl0 = *(const uint32_t*)(Bl + nb * SP + k0);
            uint32_t bl1 = *(const uint32_t*)(Bl + nb * SP + k0 + 8);
            mma_bf16(acc[t], ah0, ah1, ah2, ah3, bh0, bh1);
            mma_bf16(acc[t], ah0, ah1, ah2, ah3, bl0, bl1);
            mma_bf16(acc[t], al0, al1, al2, al3, bh0, bh1);
        }
    }
}

template <int NT>
__device__ __forceinline__ void epi_relu_to_A(float acc[][4], const float* bias,
                                              __nv_bfloat16* Ah, __nv_bfloat16* Al,
                                              int mb, int g, int tg) {
    int r0 = mb + g, r1 = mb + g + 8;
#pragma unroll
    for (int t = 0; t < NT; t++) {
        int c0 = t * 8 + tg * 2;
        float b0 = __ldg(&bias[c0]), b1 = __ldg(&bias[c0 + 1]);
        uint32_t h, l;
        split_pack(fmaxf(acc[t][0] + b0, 0.f), fmaxf(acc[t][1] + b1, 0.f), h, l);
        *(uint32_t*)(Ah + r0 * SP + c0) = h;
        *(uint32_t*)(Al + r0 * SP + c0) = l;
        split_pack(fmaxf(acc[t][2] + b0, 0.f), fmaxf(acc[t][3] + b1, 0.f), h, l);
        *(uint32_t*)(Ah + r1 * SP + c0) = h;
        *(uint32_t*)(Al + r1 * SP + c0) = l;
    }
}

// ---------------- fused 3-layer MLP on tensor pipe ----------------
// smem: Ahi/Alo [128][SP] + Bhi/Blo [128][SP] bf16 = 139264 B.
template <int IN_F, int OUT_F, bool SCATTER, bool MASK, bool XSPLIT>
__global__ void __launch_bounds__(256, 1)
k_mlp3_tc(const float* __restrict__ X,
          const __nv_bfloat16* __restrict__ Xh, const __nv_bfloat16* __restrict__ Xl,
          int rows,
          const float* __restrict__ W0f, const __nv_bfloat16* __restrict__ w0t,
          const float* __restrict__ B0,
          const __nv_bfloat16* __restrict__ w1t, const float* __restrict__ B1,
          const __nv_bfloat16* __restrict__ w2t, const float* __restrict__ B2,
          float* __restrict__ out, const int* __restrict__ slot,
          const float* __restrict__ rawn) {
    extern __shared__ __nv_bfloat16 smb[];
    __nv_bfloat16* Ah = smb;
    __nv_bfloat16* Al = smb + 128 * SP;
    __nv_bfloat16* Bh = smb + 2 * 128 * SP;
    __nv_bfloat16* Bl = smb + 3 * 128 * SP;

    const int tid  = threadIdx.x;
    const int lane = tid & 31;
    const int wid  = tid >> 5;
    const int g    = lane >> 2;
    const int tg   = lane & 3;
    const int mb   = wid * 16;
    const int row0 = blockIdx.x * 128;

    float acc[16][4];

    // ================= layer 0 =================
    if (IN_F <= 4) {
        // scalar tiny layer: thread -> (row, 64-col half)
        int row = tid & 127;
        int ch  = (tid >> 7) * 64;
        int gr  = row0 + row;
        float xv[IN_F];
#pragma unroll
        for (int i = 0; i < IN_F; i++)
            xv[i] = (gr < rows) ? __ldg(&X[(size_t)gr * IN_F + i]) : 0.f;
        uint32_t* ph = (uint32_t*)(Ah + row * SP + ch);
        uint32_t* pl = (uint32_t*)(Al + row * SP + ch);
#pragma unroll 4
        for (int j = 0; j < 32; j++) {
            int c = ch + 2 * j;
            float v0 = __ldg(&B0[c]), v1 = __ldg(&B0[c + 1]);
#pragma unroll
            for (int i = 0; i < IN_F; i++) {
                v0 += xv[i] * __ldg(&W0f[i * HF + c]);
                v1 += xv[i] * __ldg(&W0f[i * HF + c + 1]);
            }
            uint32_t h, l;
            split_pack(fmaxf(v0, 0.f), fmaxf(v1, 0.f), h, l);
            ph[j] = h;
            pl[j] = l;
        }
        __syncthreads();
    } else {
        // stage X (64 cols) into A
        if (XSPLIT) {
            const uint32_t* sh = (const uint32_t*)Xh + (size_t)row0 * 32;
            const uint32_t* sl = (const uint32_t*)Xl + (size_t)row0 * 32;
            for (int idx = tid; idx < 128 * 32; idx += 256) {
                int r = idx >> 5, w = idx & 31;
                ((uint32_t*)Ah)[r * 68 + w] = sh[idx];
                ((uint32_t*)Al)[r * 68 + w] = sl[idx];
            }
        } else {
            const float2* xs = (const float2*)(X + (size_t)row0 * 64);
            for (int idx = tid; idx < 128 * 32; idx += 256) {
                int r = idx >> 5, w = idx & 31;
                float2 v = __ldg(&xs[idx]);
                uint32_t h, l;
                split_pack(v.x, v.y, h, l);
                ((uint32_t*)Ah)[r * 68 + w] = h;
                ((uint32_t*)Al)[r * 68 + w] = l;
            }
        }
        // stage W0T [128][64]
        {
            const uint32_t* s0 = (const uint32_t*)w0t;
            for (int idx = tid; idx < 128 * 32; idx += 256) {
                int r = idx >> 5, w = idx & 31;
                ((uint32_t*)Bh)[r * 68 + w] = s0[idx];
                ((uint32_t*)Bl)[r * 68 + w] = s0[idx + 8192];
            }
        }
        __syncthreads();
#pragma unroll
        for (int t = 0; t < 16; t++)
#pragma unroll
            for (int j = 0; j < 4; j++) acc[t][j] = 0.f;
        gemm_sm<16, IN_F / 16>(Ah, Al, Bh, Bl, mb, g, tg, acc);
        epi_relu_to_A<16>(acc, B0, Ah, Al, mb, g, tg);
        __syncthreads();   // all B reads done; A (own rows) updated
    }

    // ================= layer 1 (128 -> 128) =================
    {
        const uint32_t* s1 = (const uint32_t*)w1t;
        for (int idx = tid; idx < 128 * 64; idx += 256) {
            int r = idx >> 6, w = idx & 63;
            ((uint32_t*)Bh)[r * 68 + w] = s1[idx];
            ((uint32_t*)Bl)[r * 68 + w] = s1[idx + 8192];
        }
    }
    __syncthreads();
#pragma unroll
    for (int t = 0; t < 16; t++)
#pragma unroll
        for (int j = 0; j < 4; j++) acc[t][j] = 0.f;
    gemm_sm<16, 8>(Ah, Al, Bh, Bl, mb, g, tg, acc);
    epi_relu_to_A<16>(acc, B1, Ah, Al, mb, g, tg);
    __syncthreads();

    // ================= layer 2 (128 -> OUT_F, linear) =================
    constexpr int NT2 = (OUT_F + 7) / 8;
    if (OUT_F % 8) {
        for (int idx = tid; idx < 8 * 68; idx += 256) {
            ((uint32_t*)Bh)[idx] = 0;
            ((uint32_t*)Bl)[idx] = 0;
        }
        __syncthreads();
    }
    {
        const uint32_t* s2 = (const uint32_t*)w2t;
        for (int idx = tid; idx < OUT_F * 64; idx += 256) {
            int r = idx >> 6, w = idx & 63;
            ((uint32_t*)Bh)[r * 68 + w] = s2[idx];
            ((uint32_t*)Bl)[r * 68 + w] = s2[idx + 8192];
        }
    }
    __syncthreads();
#pragma unroll
    for (int t = 0; t < NT2; t++)
#pragma unroll
        for (int j = 0; j < 4; j++) acc[t][j] = 0.f;
    gemm_sm<NT2, 8>(Ah, Al, Bh, Bl, mb, g, tg, acc);

    // epilogue -> gmem
    {
        int r0g = row0 + mb + g;
        int r1g = r0g + 8;
        bool v0 = r0g < rows, v1 = r1g < rows;
        int o0 = 0, o1 = 0;
        float m0 = 1.f, m1 = 1.f;
        if (v0) {
            o0 = SCATTER ? __ldg(&slot[r0g]) : r0g;
            if (MASK)
                m0 = ((fabsf(rawn[(size_t)r0g * 2]) + fabsf(rawn[(size_t)r0g * 2 + 1])) != 0.f) ? 1.f : 0.f;
        }
        if (v1) {
            o1 = SCATTER ? __ldg(&slot[r1g]) : r1g;
            if (MASK)
                m1 = ((fabsf(rawn[(size_t)r1g * 2]) + fabsf(rawn[(size_t)r1g * 2 + 1])) != 0.f) ? 1.f : 0.f;
        }
#pragma unroll
        for (int t = 0; t < NT2; t++) {
            int c0 = t * 8 + tg * 2;
            if (c0 < OUT_F) {
                float b0 = __ldg(&B2[c0]), b1 = __ldg(&B2[c0 + 1]);
                if (v0) {
                    out[(size_t)o0 * OUT_F + c0]     = (acc[t][0] + b0) * m0;
                    out[(size_t)o0 * OUT_F + c0 + 1] = (acc[t][1] + b1) * m0;
                }
                if (v1) {
                    out[(size_t)o1 * OUT_F + c0]     = (acc[t][2] + b0) * m1;
                    out[(size_t)o1 * OUT_F + c0 + 1] = (acc[t][3] + b1) * m1;
                }
            }
        }
    }
}

static inline int ceilDiv(int a, int b) { return (a + b - 1) / b; }

extern "C" void kernel_launch(void* const* d_in, const int* in_sizes, int n_in,
                              void* d_out, int out_size) {
    (void)in_sizes; (void)n_in; (void)out_size;
    const float* nodes = (const float*)d_in[0];
    const float* edges = (const float*)d_in[1];
    const int*   send  = (const int*)d_in[2];
    const int*   recv  = (const int*)d_in[3];
    const float* enW0 = (const float*)d_in[4],  *enb0 = (const float*)d_in[5];
    const float* enW1 = (const float*)d_in[6],  *enb1 = (const float*)d_in[7];
    const float* enW2 = (const float*)d_in[8],  *enb2 = (const float*)d_in[9];
    const float* eeW0 = (const float*)d_in[10], *eeb0 = (const float*)d_in[11];
    const float* eeW1 = (const float*)d_in[12], *eeb1 = (const float*)d_in[13];
    const float* eeW2 = (const float*)d_in[14], *eeb2 = (const float*)d_in[15];
    const float* pW0  = (const float*)d_in[16], *pb0  = (const float*)d_in[17];
    const float* pW1  = (const float*)d_in[18], *pb1  = (const float*)d_in[19];
    const float* pW2  = (const float*)d_in[20], *pb2  = (const float*)d_in[21];
    const float* dW0  = (const float*)d_in[22], *db0  = (const float*)d_in[23];
    const float* dW1  = (const float*)d_in[24], *db1  = (const float*)d_in[25];
    const float* dW2  = (const float*)d_in[26], *db2  = (const float*)d_in[27];
    float* out = (float*)d_out;

    void *pe, *pn, *pxh, *pxl, *pwt, *pdeg, *poff, *psp, *pslot;
    cudaGetSymbolAddress(&pe, g_e);
    cudaGetSymbolAddress(&pn, g_n);
    cudaGetSymbolAddress(&pxh, g_xh);
    cudaGetSymbolAddress(&pxl, g_xl);
    cudaGetSymbolAddress(&pwt, g_wt);
    cudaGetSymbolAddress(&pdeg, g_deg);
    cudaGetSymbolAddress(&poff, g_off);
    cudaGetSymbolAddress(&psp, g_sperm);
    cudaGetSymbolAddress(&pslot, g_slot);
    const __nv_bfloat16* wt = (const __nv_bfloat16*)pwt;

    const int smemB = 4 * 128 * SP * 2;  // 139264
    cudaFuncSetAttribute(k_mlp3_tc<2, 64, false, false, false>, cudaFuncAttributeMaxDynamicSharedMemorySize, smemB);
    cudaFuncSetAttribute(k_mlp3_tc<3, 64, true,  false, false>, cudaFuncAttributeMaxDynamicSharedMemorySize, smemB);
    cudaFuncSetAttribute(k_mlp3_tc<64, 64, false, false, true>, cudaFuncAttributeMaxDynamicSharedMemorySize, smemB);
    cudaFuncSetAttribute(k_mlp3_tc<64, 2, false, true, false>,  cudaFuncAttributeMaxDynamicSharedMemorySize, smemB);

    // CSR build (by receiver)
    cudaMemsetAsync(pdeg, 0, NN * sizeof(int));
    k_hist<<<ceilDiv(EE, 256), 256>>>(recv);
    k_scan<<<1, 1024>>>();
    k_scatter<<<ceilDiv(EE, 256), 256>>>(recv, send);

    // weight prep (transpose + bf16 hi/lo split), 22 slots
    WTable tb;
    tb.s[0] = {enW1, 128, 128};
    tb.s[1] = {enW2, 64, 128};
    tb.s[2] = {eeW1, 128, 128};
    tb.s[3] = {eeW2, 64, 128};
    for (int s = 0; s < 5; s++) {
        tb.s[4 + s]  = {pW0 + (size_t)s * 64 * 128,  128, 64};
        tb.s[9 + s]  = {pW1 + (size_t)s * 128 * 128, 128, 128};
        tb.s[14 + s] = {pW2 + (size_t)s * 128 * 64,  64, 128};
    }
    tb.s[19] = {dW0, 128, 64};
    tb.s[20] = {dW1, 128, 128};
    tb.s[21] = {dW2, 2, 128};
    k_prep<<<dim3(64, 22), 256>>>(tb);

    // encoders
    k_mlp3_tc<2, 64, false, false, false><<<ceilDiv(NN, 128), 256, smemB>>>(
        nodes, nullptr, nullptr, NN,
        enW0, nullptr, enb0, wt + 0 * 32768, enb1, wt + 1 * 32768, enb2,
        (float*)pn, nullptr, nullptr);
    k_mlp3_tc<3, 64, true, false, false><<<ceilDiv(EE, 128), 256, smemB>>>(
        edges, nullptr, nullptr, EE,
        eeW0, nullptr, eeb0, wt + 2 * 32768, eeb1, wt + 3 * 32768, eeb2,
        (float*)pe, (const int*)pslot, nullptr);

    // processor steps
    for (int s = 0; s < 5; s++) {
        k_agg<<<ceilDiv(NN * 32, 256), 256>>>(
            (const float*)pn, (const float*)pe, (const int*)psp, (const int*)poff,
            (__nv_bfloat16*)pxh, (__nv_bfloat16*)pxl);
        k_mlp3_tc<64, 64, false, false, true><<<ceilDiv(NN, 128), 256, smemB>>>(
            nullptr, (const __nv_bfloat16*)pxh, (const __nv_bfloat16*)pxl, NN,
            nullptr, wt + (size_t)(4 + s) * 32768, pb0 + (size_t)s * 128,
            wt + (size_t)(9 + s) * 32768, pb1 + (size_t)s * 128,
            wt + (size_t)(14 + s) * 32768, pb2 + (size_t)s * 64,
            (float*)pn, nullptr, nullptr);
    }

    // decoder + mask
    k_mlp3_tc<64, 2, false, true, false><<<ceilDiv(NN, 128), 256, smemB>>>(
        (const float*)pn, nullptr, nullptr, NN,
        nullptr, wt + 19 * 32768, db0, wt + 20 * 32768, db1, wt + 21 * 32768, db2,
        out, nullptr, nodes);
}

// round 8
// speedup vs baseline: 1.9139x; 1.2885x over previous
#include <cuda_runtime.h>
#include <cuda_bf16.h>
#include <cstdint>
#include <cstddef>

#define NN 50000
#define EE 1250000
#define LF 64
#define HF 128
#define EPSV 1e-6f
#define NB_SCAN 196   // ceil(50000/256)

// ---------------- static device scratch (no allocs allowed) ----------------
__device__ float g_e[(size_t)EE * LF];                 // edge latents (CSR order)
__device__ float g_n[(size_t)(NN + 128) * LF];         // node latents (padded)
__device__ __nv_bfloat16 g_xh[(size_t)(NN + 128) * LF];// processor input hi (padded)
__device__ __nv_bfloat16 g_xl[(size_t)(NN + 128) * LF];// processor input lo (padded)
__device__ __nv_bfloat16 g_wt[22 * 32768];             // weights: [N][K] bf16, hi then lo(+16384)
__device__ int g_deg[NN];
__device__ int g_off[NN + 1];
__device__ int g_cur[NN];
__device__ int g_bsum[NB_SCAN];
__device__ int g_slot[EE];
__device__ int g_sperm[EE];

// ---------------- CSR build ----------------
__global__ void k_hist(const int* __restrict__ recv) {
    int i = blockIdx.x * blockDim.x + threadIdx.x;
    if (i < EE) atomicAdd(&g_deg[recv[i]], 1);
}

// block-local inclusive scan -> exclusive per element; block sums saved
__global__ void k_scan1() {
    __shared__ int sh[256];
    int t = threadIdx.x;
    int i = blockIdx.x * 256 + t;
    int v = (i < NN) ? g_deg[i] : 0;
    sh[t] = v;
    __syncthreads();
#pragma unroll
    for (int d = 1; d < 256; d <<= 1) {
        int x = (t >= d) ? sh[t - d] : 0;
        __syncthreads();
        sh[t] += x;
        __syncthreads();
    }
    if (i < NN) g_off[i] = sh[t] - v;           // local exclusive
    if (t == 255) g_bsum[blockIdx.x] = sh[255]; // block total
}

__global__ void k_scan2() {
    __shared__ int sh[256];
    int t = threadIdx.x;
    int v = (t < NB_SCAN) ? g_bsum[t] : 0;
    sh[t] = v;
    __syncthreads();
#pragma unroll
    for (int d = 1; d < 256; d <<= 1) {
        int x = (t >= d) ? sh[t - d] : 0;
        __syncthreads();
        sh[t] += x;
        __syncthreads();
    }
    if (t < NB_SCAN) g_bsum[t] = sh[t] - v;     // exclusive block offsets
}

__global__ void k_scan3() {
    int i = blockIdx.x * 256 + threadIdx.x;
    if (i < NN) {
        int o = g_off[i] + g_bsum[blockIdx.x];
        g_off[i] = o;
        g_cur[i] = o;
    }
    if (i == 0) g_off[NN] = EE;
}

__global__ void k_scatter(const int* __restrict__ recv, const int* __restrict__ send) {
    int i = blockIdx.x * blockDim.x + threadIdx.x;
    if (i < EE) {
        int p = atomicAdd(&g_cur[recv[i]], 1);
        g_slot[i] = p;
        g_sperm[p] = send[i];
    }
}

// ---------------- weight prep: fp32 [K][N] -> bf16 hi/lo [N][K] ----------------
struct WSlot { const float* src; int N; int K; };
struct WTable { WSlot s[22]; };

__global__ void k_prep(WTable tab) {
    int m = blockIdx.y;
    WSlot sl = tab.s[m];
    int total = sl.N * sl.K;
    int e = blockIdx.x * 256 + threadIdx.x;
    if (e >= total) return;
    int k = e / sl.N;
    int n = e - k * sl.N;
    float v = __ldg(&sl.src[e]);
    __nv_bfloat16 h = __float2bfloat16(v);
    __nv_bfloat16 l = __float2bfloat16(v - __bfloat162float(h));
    size_t off = (size_t)m * 32768 + (size_t)n * sl.K + k;
    g_wt[off] = h;
    g_wt[off + 16384] = l;
}

// ---------------- softmax aggregation: 2 online streams per lane ----------------
__global__ void k_agg(const float* __restrict__ n, const float* __restrict__ e,
                      const int* __restrict__ sp, const int* __restrict__ off,
                      __nv_bfloat16* __restrict__ xh, __nv_bfloat16* __restrict__ xl) {
    int w = (blockIdx.x * blockDim.x + threadIdx.x) >> 5;
    int lane = threadIdx.x & 31;
    if (w >= NN) return;
    int p0 = __ldg(&off[w]);
    int p1 = __ldg(&off[w + 1]);

    const float NEG = -3.0e38f;
    float mxA0 = NEG, mxA1 = NEG, mxB0 = NEG, mxB1 = NEG;
    float saA0 = 0.f, sbA0 = 0.f, saA1 = 0.f, sbA1 = 0.f;
    float saB0 = 0.f, sbB0 = 0.f, saB1 = 0.f, sbB1 = 0.f;

    int p = p0;
    for (; p + 1 < p1; p += 2) {
        int sA = __ldg(&sp[p]);
        int sB = __ldg(&sp[p + 1]);
        size_t eA = (size_t)p * LF, eB = (size_t)(p + 1) * LF;
        size_t nA = (size_t)sA * LF, nB = (size_t)sB * LF;
        float mA0 = fmaxf(n[nA + lane]      + e[eA + lane],      0.f) + EPSV;
        float mA1 = fmaxf(n[nA + lane + 32] + e[eA + lane + 32], 0.f) + EPSV;
        float mB0 = fmaxf(n[nB + lane]      + e[eB + lane],      0.f) + EPSV;
        float mB1 = fmaxf(n[nB + lane + 32] + e[eB + lane + 32], 0.f) + EPSV;

        float nm, c, t;
        nm = fmaxf(mxA0, mA0); c = __expf(mxA0 - nm); t = __expf(mA0 - nm);
        saA0 = saA0 * c + t; sbA0 = sbA0 * c + t * mA0; mxA0 = nm;
        nm = fmaxf(mxA1, mA1); c = __expf(mxA1 - nm); t = __expf(mA1 - nm);
        saA1 = saA1 * c + t; sbA1 = sbA1 * c + t * mA1; mxA1 = nm;
        nm = fmaxf(mxB0, mB0); c = __expf(mxB0 - nm); t = __expf(mB0 - nm);
        saB0 = saB0 * c + t; sbB0 = sbB0 * c + t * mB0; mxB0 = nm;
        nm = fmaxf(mxB1, mB1); c = __expf(mxB1 - nm); t = __expf(mB1 - nm);
        saB1 = saB1 * c + t; sbB1 = sbB1 * c + t * mB1; mxB1 = nm;
    }
    if (p < p1) {
        int sA = __ldg(&sp[p]);
        size_t eA = (size_t)p * LF, nA = (size_t)sA * LF;
        float mA0 = fmaxf(n[nA + lane]      + e[eA + lane],      0.f) + EPSV;
        float mA1 = fmaxf(n[nA + lane + 32] + e[eA + lane + 32], 0.f) + EPSV;
        float nm, c, t;
        nm = fmaxf(mxA0, mA0); c = __expf(mxA0 - nm); t = __expf(mA0 - nm);
        saA0 = saA0 * c + t; sbA0 = sbA0 * c + t * mA0; mxA0 = nm;
        nm = fmaxf(mxA1, mA1); c = __expf(mxA1 - nm); t = __expf(mA1 - nm);
        saA1 = saA1 * c + t; sbA1 = sbA1 * c + t * mA1; mxA1 = nm;
    }

    // merge streams (finite sentinel -> no NaN)
    float nm0 = fmaxf(mxA0, mxB0);
    float sa0 = saA0 * __expf(mxA0 - nm0) + saB0 * __expf(mxB0 - nm0);
    float sb0 = sbA0 * __expf(mxA0 - nm0) + sbB0 * __expf(mxB0 - nm0);
    float nm1 = fmaxf(mxA1, mxB1);
    float sa1 = saA1 * __expf(mxA1 - nm1) + saB1 * __expf(mxB1 - nm1);
    float sb1 = sbA1 * __expf(mxA1 - nm1) + sbB1 * __expf(mxB1 - nm1);

    float a0 = (sa0 > 0.f) ? sb0 / sa0 : 0.f;
    float a1 = (sa1 > 0.f) ? sb1 / sa1 : 0.f;
    size_t nb = (size_t)w * LF;
    float x0 = n[nb + lane]      + a0;
    float x1 = n[nb + lane + 32] + a1;
    __nv_bfloat16 h0 = __float2bfloat16(x0);
    __nv_bfloat16 h1 = __float2bfloat16(x1);
    xh[nb + lane]      = h0;
    xl[nb + lane]      = __float2bfloat16(x0 - __bfloat162float(h0));
    xh[nb + lane + 32] = h1;
    xl[nb + lane + 32] = __float2bfloat16(x1 - __bfloat162float(h1));
}

// ---------------- mma.sync helpers ----------------
__device__ __forceinline__ void mma_bf16(float* c, uint32_t a0, uint32_t a1, uint32_t a2, uint32_t a3,
                                         uint32_t b0, uint32_t b1) {
    asm volatile("mma.sync.aligned.m16n8k16.row.col.f32.bf16.bf16.f32 "
                 "{%0,%1,%2,%3}, {%4,%5,%6,%7}, {%8,%9}, {%0,%1,%2,%3};"
                 : "+f"(c[0]), "+f"(c[1]), "+f"(c[2]), "+f"(c[3])
                 : "r"(a0), "r"(a1), "r"(a2), "r"(a3), "r"(b0), "r"(b1));
}

__device__ __forceinline__ void split_pack(float a, float b, uint32_t& hi, uint32_t& lo) {
    __nv_bfloat16 ha = __float2bfloat16(a), hb = __float2bfloat16(b);
    float ra = a - __bfloat162float(ha), rb = b - __bfloat162float(hb);
    hi = (uint32_t)__bfloat16_as_ushort(ha) | ((uint32_t)__bfloat16_as_ushort(hb) << 16);
    lo = (uint32_t)__bfloat16_as_ushort(__float2bfloat16(ra)) |
         ((uint32_t)__bfloat16_as_ushort(__float2bfloat16(rb)) << 16);
}

#define SP 136  // smem row stride (bf16)

// 3-pass bf16 GEMM fragment loop; B has NT local 8-row tiles, acc[t] matches
template <int NT, int KST>
__device__ __forceinline__ void gemm_half(const __nv_bfloat16* Ah, const __nv_bfloat16* Al,
                                          const __nv_bfloat16* Bh, const __nv_bfloat16* Bl,
                                          int mb, int g, int tg, float (*acc)[4]) {
#pragma unroll
    for (int k = 0; k < KST; k++) {
        int k0 = k * 16 + tg * 2;
        uint32_t ah0 = *(const uint32_t*)(Ah + (mb + g) * SP + k0);
        uint32_t ah1 = *(const uint32_t*)(Ah + (mb + g + 8) * SP + k0);
        uint32_t ah2 = *(const uint32_t*)(Ah + (mb + g) * SP + k0 + 8);
        uint32_t ah3 = *(const uint32_t*)(Ah + (mb + g + 8) * SP + k0 + 8);
        uint32_t al0 = *(const uint32_t*)(Al + (mb + g) * SP + k0);
        uint32_t al1 = *(const uint32_t*)(Al + (mb + g + 8) * SP + k0);
        uint32_t al2 = *(const uint32_t*)(Al + (mb + g) * SP + k0 + 8);
        uint32_t al3 = *(const uint32_t*)(Al + (mb + g + 8) * SP + k0 + 8);
#pragma unroll
        for (int t = 0; t < NT; t++) {
            int nb = t * 8 + g;
            uint32_t bh0 = *(const uint32_t*)(Bh + nb * SP + k0);
            uint32_t bh1 = *(const uint32_t*)(Bh + nb * SP + k0 + 8);
            uint32_t bl0 = *(const uint32_t*)(Bl + nb * SP + k0);
            uint32_t bl1 = *(const uint32_t*)(Bl + nb * SP + k0 + 8);
            mma_bf16(acc[t], ah0, ah1, ah2, ah3, bh0, bh1);
            mma_bf16(acc[t], ah0, ah1, ah2, ah3, bl0, bl1);
            mma_bf16(acc[t], al0, al1, al2, al3, bh0, bh1);
        }
    }
}

template <int NT>
__device__ __forceinline__ void epi_relu_to_A(float (*acc)[4], const float* bias,
                                              __nv_bfloat16* Ah, __nv_bfloat16* Al,
                                              int mb, int g, int tg) {
    int r0 = mb + g, r1 = mb + g + 8;
#pragma unroll
    for (int t = 0; t < NT; t++) {
        int c0 = t * 8 + tg * 2;
        float b0 = __ldg(&bias[c0]), b1 = __ldg(&bias[c0 + 1]);
        uint32_t h, l;
        split_pack(fmaxf(acc[t][0] + b0, 0.f), fmaxf(acc[t][1] + b1, 0.f), h, l);
        *(uint32_t*)(Ah + r0 * SP + c0) = h;
        *(uint32_t*)(Al + r0 * SP + c0) = l;
        split_pack(fmaxf(acc[t][2] + b0, 0.f), fmaxf(acc[t][3] + b1, 0.f), h, l);
        *(uint32_t*)(Ah + r1 * SP + c0) = h;
        *(uint32_t*)(Al + r1 * SP + c0) = l;
    }
}

// ---------------- fused 3-layer MLP on tensor pipe, 2 CTAs/SM ----------------
// smem: Ah/Al [128][SP] + Bh/Bl [64][SP] bf16 = 104448 B.
template <int IN_F, int OUT_F, bool SCATTER, bool MASK, bool XSPLIT>
__global__ void __launch_bounds__(256, 2)
k_mlp3_tc(const float* __restrict__ X,
          const __nv_bfloat16* __restrict__ Xh, const __nv_bfloat16* __restrict__ Xl,
          int rows,
          const float* __restrict__ W0f, const __nv_bfloat16* __restrict__ w0t,
          const float* __restrict__ B0,
          const __nv_bfloat16* __restrict__ w1t, const float* __restrict__ B1,
          const __nv_bfloat16* __restrict__ w2t, const float* __restrict__ B2,
          float* __restrict__ out, const int* __restrict__ slot,
          const float* __restrict__ rawn) {
    extern __shared__ __nv_bfloat16 smb[];
    __nv_bfloat16* Ah = smb;
    __nv_bfloat16* Al = smb + 128 * SP;
    __nv_bfloat16* Bh = smb + 2 * 128 * SP;
    __nv_bfloat16* Bl = smb + (2 * 128 + 64) * SP;

    const int tid  = threadIdx.x;
    const int lane = tid & 31;
    const int wid  = tid >> 5;
    const int g    = lane >> 2;
    const int tg   = lane & 3;
    const int mb   = wid * 16;
    const int row0 = blockIdx.x * 128;

    float acc[16][4];

    // ================= layer 0 =================
    if (IN_F <= 4) {
        int row = tid & 127;
        int ch  = (tid >> 7) * 64;
        int gr  = row0 + row;
        float xv[IN_F];
#pragma unroll
        for (int i = 0; i < IN_F; i++)
            xv[i] = (gr < rows) ? __ldg(&X[(size_t)gr * IN_F + i]) : 0.f;
        uint32_t* ph = (uint32_t*)(Ah + row * SP + ch);
        uint32_t* pl = (uint32_t*)(Al + row * SP + ch);
#pragma unroll 4
        for (int j = 0; j < 32; j++) {
            int c = ch + 2 * j;
            float v0 = __ldg(&B0[c]), v1 = __ldg(&B0[c + 1]);
#pragma unroll
            for (int i = 0; i < IN_F; i++) {
                v0 += xv[i] * __ldg(&W0f[i * HF + c]);
                v1 += xv[i] * __ldg(&W0f[i * HF + c + 1]);
            }
            uint32_t h, l;
            split_pack(fmaxf(v0, 0.f), fmaxf(v1, 0.f), h, l);
            ph[j] = h;
            pl[j] = l;
        }
        __syncthreads();
    } else {
        // stage X (64 cols) into A
        if (XSPLIT) {
            const uint32_t* shp = (const uint32_t*)Xh + (size_t)row0 * 32;
            const uint32_t* slp = (const uint32_t*)Xl + (size_t)row0 * 32;
            for (int idx = tid; idx < 128 * 32; idx += 256) {
                int r = idx >> 5, w = idx & 31;
                ((uint32_t*)Ah)[r * 68 + w] = shp[idx];
                ((uint32_t*)Al)[r * 68 + w] = slp[idx];
            }
        } else {
            const float2* xs = (const float2*)(X + (size_t)row0 * 64);
            for (int idx = tid; idx < 128 * 32; idx += 256) {
                int r = idx >> 5, w = idx & 31;
                float2 v = __ldg(&xs[idx]);
                uint32_t h, l;
                split_pack(v.x, v.y, h, l);
                ((uint32_t*)Ah)[r * 68 + w] = h;
                ((uint32_t*)Al)[r * 68 + w] = l;
            }
        }
#pragma unroll
        for (int t = 0; t < 16; t++)
#pragma unroll
            for (int j = 0; j < 4; j++) acc[t][j] = 0.f;
        // layer0 GEMM (K=64), B = w0t [128][64] in two 64-N halves
        const uint32_t* s0 = (const uint32_t*)w0t;
#pragma unroll
        for (int nh = 0; nh < 2; nh++) {
            __syncthreads();
            for (int idx = tid; idx < 64 * 32; idx += 256) {
                int r = idx >> 5, w = idx & 31;
                ((uint32_t*)Bh)[r * 68 + w] = s0[(nh * 64 + r) * 32 + w];
                ((uint32_t*)Bl)[r * 68 + w] = s0[(nh * 64 + r) * 32 + w + 8192];
            }
            __syncthreads();
            gemm_half<8, 4>(Ah, Al, Bh, Bl, mb, g, tg, acc + nh * 8);
        }
        __syncthreads();
        epi_relu_to_A<16>(acc, B0, Ah, Al, mb, g, tg);
        __syncthreads();
    }

    // ================= layer 1 (128 -> 128), two 64-N halves =================
#pragma unroll
    for (int t = 0; t < 16; t++)
#pragma unroll
        for (int j = 0; j < 4; j++) acc[t][j] = 0.f;
    {
        const uint32_t* s1 = (const uint32_t*)w1t;
#pragma unroll
        for (int nh = 0; nh < 2; nh++) {
            if (nh) __syncthreads();
            for (int idx = tid; idx < 64 * 64; idx += 256) {
                int r = idx >> 6, w = idx & 63;
                ((uint32_t*)Bh)[r * 68 + w] = s1[(nh * 64 + r) * 64 + w];
                ((uint32_t*)Bl)[r * 68 + w] = s1[(nh * 64 + r) * 64 + w + 8192];
            }
            __syncthreads();
            gemm_half<8, 8>(Ah, Al, Bh, Bl, mb, g, tg, acc + nh * 8);
        }
    }
    __syncthreads();
    epi_relu_to_A<16>(acc, B1, Ah, Al, mb, g, tg);
    __syncthreads();

    // ================= layer 2 (128 -> OUT_F, linear) =================
    constexpr int NT2 = (OUT_F + 7) / 8;
    if (OUT_F % 8) {
        for (int idx = tid; idx < 8 * 68; idx += 256) {
            ((uint32_t*)Bh)[idx] = 0;
            ((uint32_t*)Bl)[idx] = 0;
        }
        __syncthreads();
    }
    {
        const uint32_t* s2 = (const uint32_t*)w2t;
        for (int idx = tid; idx < OUT_F * 64; idx += 256) {
            int r = idx >> 6, w = idx & 63;
            ((uint32_t*)Bh)[r * 68 + w] = s2[idx];
            ((uint32_t*)Bl)[r * 68 + w] = s2[idx + 8192];
        }
    }
    __syncthreads();
#pragma unroll
    for (int t = 0; t < NT2; t++)
#pragma unroll
        for (int j = 0; j < 4; j++) acc[t][j] = 0.f;
    gemm_half<NT2, 8>(Ah, Al, Bh, Bl, mb, g, tg, acc);

    // epilogue -> gmem
    {
        int r0g = row0 + mb + g;
        int r1g = r0g + 8;
        bool v0 = r0g < rows, v1 = r1g < rows;
        int o0 = 0, o1 = 0;
        float m0 = 1.f, m1 = 1.f;
        if (v0) {
            o0 = SCATTER ? __ldg(&slot[r0g]) : r0g;
            if (MASK)
                m0 = ((fabsf(rawn[(size_t)r0g * 2]) + fabsf(rawn[(size_t)r0g * 2 + 1])) != 0.f) ? 1.f : 0.f;
        }
        if (v1) {
            o1 = SCATTER ? __ldg(&slot[r1g]) : r1g;
            if (MASK)
                m1 = ((fabsf(rawn[(size_t)r1g * 2]) + fabsf(rawn[(size_t)r1g * 2 + 1])) != 0.f) ? 1.f : 0.f;
        }
#pragma unroll
        for (int t = 0; t < NT2; t++) {
            int c0 = t * 8 + tg * 2;
            if (c0 < OUT_F) {
                float b0 = __ldg(&B2[c0]), b1 = __ldg(&B2[c0 + 1]);
                if (v0) {
                    out[(size_t)o0 * OUT_F + c0]     = (acc[t][0] + b0) * m0;
                    out[(size_t)o0 * OUT_F + c0 + 1] = (acc[t][1] + b1) * m0;
                }
                if (v1) {
                    out[(size_t)o1 * OUT_F + c0]     = (acc[t][2] + b0) * m1;
                    out[(size_t)o1 * OUT_F + c0 + 1] = (acc[t][3] + b1) * m1;
                }
            }
        }
    }
}

static inline int ceilDiv(int a, int b) { return (a + b - 1) / b; }

extern "C" void kernel_launch(void* const* d_in, const int* in_sizes, int n_in,
                              void* d_out, int out_size) {
    (void)in_sizes; (void)n_in; (void)out_size;
    const float* nodes = (const float*)d_in[0];
    const float* edges = (const float*)d_in[1];
    const int*   send  = (const int*)d_in[2];
    const int*   recv  = (const int*)d_in[3];
    const float* enW0 = (const float*)d_in[4],  *enb0 = (const float*)d_in[5];
    const float* enW1 = (const float*)d_in[6],  *enb1 = (const float*)d_in[7];
    const float* enW2 = (const float*)d_in[8],  *enb2 = (const float*)d_in[9];
    const float* eeW0 = (const float*)d_in[10], *eeb0 = (const float*)d_in[11];
    const float* eeW1 = (const float*)d_in[12], *eeb1 = (const float*)d_in[13];
    const float* eeW2 = (const float*)d_in[14], *eeb2 = (const float*)d_in[15];
    const float* pW0  = (const float*)d_in[16], *pb0  = (const float*)d_in[17];
    const float* pW1  = (const float*)d_in[18], *pb1  = (const float*)d_in[19];
    const float* pW2  = (const float*)d_in[20], *pb2  = (const float*)d_in[21];
    const float* dW0  = (const float*)d_in[22], *db0  = (const float*)d_in[23];
    const float* dW1  = (const float*)d_in[24], *db1  = (const float*)d_in[25];
    const float* dW2  = (const float*)d_in[26], *db2  = (const float*)d_in[27];
    float* out = (float*)d_out;

    void *pe, *pn, *pxh, *pxl, *pwt, *pdeg, *poff, *psp, *pslot;
    cudaGetSymbolAddress(&pe, g_e);
    cudaGetSymbolAddress(&pn, g_n);
    cudaGetSymbolAddress(&pxh, g_xh);
    cudaGetSymbolAddress(&pxl, g_xl);
    cudaGetSymbolAddress(&pwt, g_wt);
    cudaGetSymbolAddress(&pdeg, g_deg);
    cudaGetSymbolAddress(&poff, g_off);
    cudaGetSymbolAddress(&psp, g_sperm);
    cudaGetSymbolAddress(&pslot, g_slot);
    const __nv_bfloat16* wt = (const __nv_bfloat16*)pwt;

    const int smemB = (2 * 128 + 2 * 64) * SP * 2;  // 104448
    cudaFuncSetAttribute(k_mlp3_tc<2, 64, false, false, false>, cudaFuncAttributeMaxDynamicSharedMemorySize, smemB);
    cudaFuncSetAttribute(k_mlp3_tc<3, 64, true,  false, false>, cudaFuncAttributeMaxDynamicSharedMemorySize, smemB);
    cudaFuncSetAttribute(k_mlp3_tc<64, 64, false, false, true>, cudaFuncAttributeMaxDynamicSharedMemorySize, smemB);
    cudaFuncSetAttribute(k_mlp3_tc<64, 2, false, true, false>,  cudaFuncAttributeMaxDynamicSharedMemorySize, smemB);

    // CSR build (by receiver)
    cudaMemsetAsync(pdeg, 0, NN * sizeof(int));
    k_hist<<<ceilDiv(EE, 256), 256>>>(recv);
    k_scan1<<<NB_SCAN, 256>>>();
    k_scan2<<<1, 256>>>();
    k_scan3<<<NB_SCAN, 256>>>();
    k_scatter<<<ceilDiv(EE, 256), 256>>>(recv, send);

    // weight prep (transpose + bf16 hi/lo split), 22 slots
    WTable tb;
    tb.s[0] = {enW1, 128, 128};
    tb.s[1] = {enW2, 64, 128};
    tb.s[2] = {eeW1, 128, 128};
    tb.s[3] = {eeW2, 64, 128};
    for (int s = 0; s < 5; s++) {
        tb.s[4 + s]  = {pW0 + (size_t)s * 64 * 128,  128, 64};
        tb.s[9 + s]  = {pW1 + (size_t)s * 128 * 128, 128, 128};
        tb.s[14 + s] = {pW2 + (size_t)s * 128 * 64,  64, 128};
    }
    tb.s[19] = {dW0, 128, 64};
    tb.s[20] = {dW1, 128, 128};
    tb.s[21] = {dW2, 2, 128};
    k_prep<<<dim3(64, 22), 256>>>(tb);

    // encoders
    k_mlp3_tc<2, 64, false, false, false><<<ceilDiv(NN, 128), 256, smemB>>>(
        nodes, nullptr, nullptr, NN,
        enW0, wt + 0 * 32768, enb0, wt + 0 * 32768, enb1, wt + 1 * 32768, enb2,
        (float*)pn, nullptr, nullptr);
    k_mlp3_tc<3, 64, true, false, false><<<ceilDiv(EE, 128), 256, smemB>>>(
        edges, nullptr, nullptr, EE,
        eeW0, wt + 2 * 32768, eeb0, wt + 2 * 32768, eeb1, wt + 3 * 32768, eeb2,
        (float*)pe, (const int*)pslot, nullptr);

    // processor steps
    for (int s = 0; s < 5; s++) {
        k_agg<<<ceilDiv(NN * 32, 256), 256>>>(
            (const float*)pn, (const float*)pe, (const int*)psp, (const int*)poff,
            (__nv_bfloat16*)pxh, (__nv_bfloat16*)pxl);
        k_mlp3_tc<64, 64, false, false, true><<<ceilDiv(NN, 128), 256, smemB>>>(
            nullptr, (const __nv_bfloat16*)pxh, (const __nv_bfloat16*)pxl, NN,
            nullptr, wt + (size_t)(4 + s) * 32768, pb0 + (size_t)s * 128,
            wt + (size_t)(9 + s) * 32768, pb1 + (size_t)s * 128,
            wt + (size_t)(14 + s) * 32768, pb2 + (size_t)s * 64,
            (float*)pn, nullptr, nullptr);
    }

    // decoder + mask
    k_mlp3_tc<64, 2, false, true, false><<<ceilDiv(NN, 128), 256, smemB>>>(
        (const float*)pn, nullptr, nullptr, NN,
        nullptr, wt + 19 * 32768, db0, wt + 20 * 32768, db1, wt + 21 * 32768, db2,
        out, nullptr, nodes);
}